// round 1
// baseline (speedup 1.0000x reference)
#include <cuda_runtime.h>

#define B_SZ  8
#define C_CH  256
#define N_PIX 4096
#define GROUPS 8
#define CPG   (C_CH / GROUPS)   // 32

// ---------------- scratch (device globals: alloc-free rule) ----------------
__device__ float g_xn  [B_SZ * C_CH     * N_PIX];                 // 32 MB
__device__ float g_qkv [B_SZ * 3 * C_CH * N_PIX];                 // 100 MB
__device__ float g_attn[(size_t)B_SZ * N_PIX * N_PIX];            // 512 MB
__device__ float g_av  [B_SZ * C_CH     * N_PIX];                 // 32 MB

// ---------------- GroupNorm: one block per (batch, group) ----------------
__global__ void gn_kernel(const float* __restrict__ x,
                          const float* __restrict__ gw,
                          const float* __restrict__ gb,
                          float* __restrict__ xn) {
    int batch = blockIdx.x >> 3;
    int g     = blockIdx.x & 7;
    const size_t base = ((size_t)batch * C_CH + (size_t)g * CPG) * N_PIX;
    const float* xp = x + base;
    const int TOT = CPG * N_PIX;   // 131072

    float s = 0.f, s2 = 0.f;
    for (int i = threadIdx.x; i < TOT; i += blockDim.x) {
        float v = xp[i]; s += v; s2 += v * v;
    }
    #pragma unroll
    for (int o = 16; o > 0; o >>= 1) {
        s  += __shfl_xor_sync(0xFFFFFFFFu, s,  o);
        s2 += __shfl_xor_sync(0xFFFFFFFFu, s2, o);
    }
    __shared__ float shs[8], shs2[8];
    __shared__ float s_mean, s_inv;
    int wid = threadIdx.x >> 5, lid = threadIdx.x & 31;
    if (lid == 0) { shs[wid] = s; shs2[wid] = s2; }
    __syncthreads();
    if (threadIdx.x == 0) {
        float ts = 0.f, ts2 = 0.f;
        #pragma unroll
        for (int i = 0; i < 8; i++) { ts += shs[i]; ts2 += shs2[i]; }
        float mean = ts / (float)TOT;
        float var  = ts2 / (float)TOT - mean * mean;
        s_mean = mean;
        s_inv  = rsqrtf(var + 1e-5f);
    }
    __syncthreads();
    float mean = s_mean, inv = s_inv;
    for (int i = threadIdx.x; i < TOT; i += blockDim.x) {
        int c = g * CPG + (i >> 12);           // i / N_PIX
        xn[base + i] = (xp[i] - mean) * inv * gw[c] + gb[c];
    }
}

// ---------------- generic 64x64 fp32 SGEMM ----------------
// C[m,n] = alpha * sum_k A(m,k)*B(k,n)  (+ bias[m]) (+ resid[m,n])
// A(m,k) = ATRANS ? A[k*lda + m] : A[m*lda + k]
// B(k,n) = BTRANS ? B[n*ldb + k] : B[k*ldb + n]
// EPI: 0 = alpha only, 1 = + bias[m], 2 = + bias[m] + resid
template <int ATRANS, int BTRANS, int EPI>
__global__ void __launch_bounds__(256)
gemm64(const float* __restrict__ A, const float* __restrict__ B,
       float* __restrict__ C,
       int M, int N, int K, int lda, int ldb, int ldc,
       size_t sA, size_t sB, size_t sC,
       const float* __restrict__ bias, const float* __restrict__ resid,
       float alpha) {
    __shared__ float As[16][68];
    __shared__ float Bs[16][68];

    const int bn = blockIdx.x * 64;
    const int bm = blockIdx.y * 64;
    const int bz = blockIdx.z;
    A += sA * bz; B += sB * bz; C += sC * bz;
    const float* Rz = (EPI == 2) ? (resid + sC * bz) : nullptr;

    const int tid = threadIdx.x;
    const int tx  = tid & 15;    // n
    const int ty  = tid >> 4;    // m

    float acc[4][4] = {};

    for (int k0 = 0; k0 < K; k0 += 16) {
        #pragma unroll
        for (int r = 0; r < 4; r++) {
            int idx = tid + 256 * r;
            if (ATRANS) {
                int kk = idx >> 6, mm = idx & 63;
                As[kk][mm] = A[(size_t)(k0 + kk) * lda + (bm + mm)];
            } else {
                int mm = idx >> 4, kk = idx & 15;
                As[kk][mm] = A[(size_t)(bm + mm) * lda + (k0 + kk)];
            }
        }
        #pragma unroll
        for (int r = 0; r < 4; r++) {
            int idx = tid + 256 * r;
            if (BTRANS) {
                int nn = idx >> 4, kk = idx & 15;
                Bs[kk][nn] = B[(size_t)(bn + nn) * ldb + (k0 + kk)];
            } else {
                int kk = idx >> 6, nn = idx & 63;
                Bs[kk][nn] = B[(size_t)(k0 + kk) * ldb + (bn + nn)];
            }
        }
        __syncthreads();
        #pragma unroll
        for (int kk = 0; kk < 16; kk++) {
            float a[4], b[4];
            #pragma unroll
            for (int i = 0; i < 4; i++) a[i] = As[kk][ty * 4 + i];
            #pragma unroll
            for (int j = 0; j < 4; j++) b[j] = Bs[kk][tx * 4 + j];
            #pragma unroll
            for (int i = 0; i < 4; i++)
                #pragma unroll
                for (int j = 0; j < 4; j++)
                    acc[i][j] = fmaf(a[i], b[j], acc[i][j]);
        }
        __syncthreads();
    }

    #pragma unroll
    for (int i = 0; i < 4; i++) {
        int m = bm + ty * 4 + i;
        float bv = (EPI >= 1) ? bias[m] : 0.f;
        #pragma unroll
        for (int j = 0; j < 4; j++) {
            int n = bn + tx * 4 + j;
            float v = acc[i][j] * alpha + bv;
            if (EPI == 2) v += Rz[(size_t)m * ldc + n];
            C[(size_t)m * ldc + n] = v;
        }
    }
}

// ---------------- row softmax over 4096, one block per row ----------------
__global__ void __launch_bounds__(256) softmax_kernel(float* __restrict__ attn) {
    float* p = attn + (size_t)blockIdx.x * N_PIX;
    const int t = threadIdx.x;
    float v[16];
    float mx = -1e30f;
    #pragma unroll
    for (int r = 0; r < 16; r++) { v[r] = p[t + 256 * r]; mx = fmaxf(mx, v[r]); }

    __shared__ float red[8];
    __shared__ float bval;
    int wid = t >> 5, lid = t & 31;

    #pragma unroll
    for (int o = 16; o > 0; o >>= 1) mx = fmaxf(mx, __shfl_xor_sync(0xFFFFFFFFu, mx, o));
    if (lid == 0) red[wid] = mx;
    __syncthreads();
    if (t == 0) {
        float m = red[0];
        #pragma unroll
        for (int i = 1; i < 8; i++) m = fmaxf(m, red[i]);
        bval = m;
    }
    __syncthreads();
    mx = bval;

    float sum = 0.f;
    #pragma unroll
    for (int r = 0; r < 16; r++) { v[r] = __expf(v[r] - mx); sum += v[r]; }
    #pragma unroll
    for (int o = 16; o > 0; o >>= 1) sum += __shfl_xor_sync(0xFFFFFFFFu, sum, o);
    __syncthreads();
    if (lid == 0) red[wid] = sum;
    __syncthreads();
    if (t == 0) {
        float s = 0.f;
        #pragma unroll
        for (int i = 0; i < 8; i++) s += red[i];
        bval = 1.0f / s;
    }
    __syncthreads();
    float inv = bval;
    #pragma unroll
    for (int r = 0; r < 16; r++) p[t + 256 * r] = v[r] * inv;
}

// ---------------- launch ----------------
extern "C" void kernel_launch(void* const* d_in, const int* in_sizes, int n_in,
                              void* d_out, int out_size) {
    const float* x      = (const float*)d_in[0];
    const float* gn_w   = (const float*)d_in[1];
    const float* gn_b   = (const float*)d_in[2];
    const float* qkv_w  = (const float*)d_in[3];
    const float* qkv_b  = (const float*)d_in[4];
    const float* proj_w = (const float*)d_in[5];
    const float* proj_b = (const float*)d_in[6];
    float* out = (float*)d_out;

    float *xn, *qkv, *attn, *av;
    cudaGetSymbolAddress((void**)&xn,   g_xn);
    cudaGetSymbolAddress((void**)&qkv,  g_qkv);
    cudaGetSymbolAddress((void**)&attn, g_attn);
    cudaGetSymbolAddress((void**)&av,   g_av);

    const size_t sXN   = (size_t)C_CH * N_PIX;       // 1M
    const size_t sQKV  = (size_t)3 * C_CH * N_PIX;   // 3M
    const size_t sATT  = (size_t)N_PIX * N_PIX;      // 16M

    // 1) GroupNorm
    gn_kernel<<<B_SZ * GROUPS, 256>>>(x, gn_w, gn_b, xn);

    // 2) QKV: [768,256] x [256,4096] per batch, +bias
    gemm64<0, 0, 1><<<dim3(N_PIX / 64, (3 * C_CH) / 64, B_SZ), 256>>>(
        qkv_w, xn, qkv, 3 * C_CH, N_PIX, C_CH, C_CH, N_PIX, N_PIX,
        0, sXN, sQKV, qkv_b, nullptr, 1.0f);

    // 3) scores: S[i,j] = (1/16) * sum_c q[c,i] k[c,j]
    gemm64<1, 0, 0><<<dim3(N_PIX / 64, N_PIX / 64, B_SZ), 256>>>(
        qkv /*q*/, qkv + (size_t)C_CH * N_PIX /*k*/, attn,
        N_PIX, N_PIX, C_CH, N_PIX, N_PIX, N_PIX,
        sQKV, sQKV, sATT, nullptr, nullptr, 0.0625f);

    // 4) softmax rows
    softmax_kernel<<<B_SZ * N_PIX, 256>>>(attn);

    // 5) AV: O[c,i] = sum_m v[c,m] * attn[i,m]
    gemm64<0, 1, 0><<<dim3(N_PIX / 64, C_CH / 64, B_SZ), 256>>>(
        qkv + (size_t)2 * C_CH * N_PIX /*v*/, attn, av,
        C_CH, N_PIX, N_PIX, N_PIX, N_PIX, N_PIX,
        sQKV, sATT, sXN, nullptr, nullptr, 1.0f);

    // 6) proj + bias + residual
    gemm64<0, 0, 2><<<dim3(N_PIX / 64, C_CH / 64, B_SZ), 256>>>(
        proj_w, av, out, C_CH, N_PIX, C_CH, C_CH, N_PIX, N_PIX,
        0, sXN, sXN, proj_b, x, 1.0f);
}

// round 3
// speedup vs baseline: 2.4436x; 2.4436x over previous
#include <cuda_runtime.h>
#include <cuda_bf16.h>
#include <cstdint>

#define B_SZ  8
#define C_CH  256
#define N_PIX 4096

typedef unsigned short u16;

// ---------------- scratch (device globals) ----------------
__device__ u16 g_wh[768 * 256],  g_wl[768 * 256];
__device__ u16 g_ph[256 * 256],  g_pl[256 * 256];
__device__ u16 g_xnh[B_SZ * N_PIX * C_CH], g_xnl[B_SZ * N_PIX * C_CH];   // xn^T [b][n][c]
__device__ u16 g_qTh[B_SZ * N_PIX * C_CH], g_qTl[B_SZ * N_PIX * C_CH];
__device__ u16 g_kTh[B_SZ * N_PIX * C_CH], g_kTl[B_SZ * N_PIX * C_CH];
__device__ u16 g_vh [B_SZ * C_CH * N_PIX], g_vl [B_SZ * C_CH * N_PIX];   // v [b][c][m]
__device__ float g_S[(size_t)B_SZ * N_PIX * N_PIX];                      // 512MB
__device__ u16 g_ah[(size_t)B_SZ * N_PIX * N_PIX];                       // 256MB
__device__ u16 g_al[(size_t)B_SZ * N_PIX * N_PIX];                       // 256MB
__device__ u16 g_oh[B_SZ * N_PIX * C_CH], g_ol[B_SZ * N_PIX * C_CH];     // O [b][i][c]

// ---------------- helpers ----------------
__device__ __forceinline__ uint32_t smem_u32(const void* p) {
    uint32_t a;
    asm("{ .reg .u64 t; cvta.to.shared.u64 t, %1; cvt.u32.u64 %0, t; }" : "=r"(a) : "l"(p));
    return a;
}
__device__ __forceinline__ u16 bfbits(float v) {
    return __bfloat16_as_ushort(__float2bfloat16_rn(v));
}
__device__ __forceinline__ float bfval(u16 u) { return __uint_as_float(((uint32_t)u) << 16); }
__device__ __forceinline__ uint32_t pk(u16 a, u16 b) { return (uint32_t)a | ((uint32_t)b << 16); }
__device__ __forceinline__ void split2(float f0, float f1, uint32_t& h, uint32_t& l) {
    u16 h0 = bfbits(f0), h1 = bfbits(f1);
    u16 l0 = bfbits(f0 - bfval(h0)), l1 = bfbits(f1 - bfval(h1));
    h = pk(h0, h1); l = pk(l0, l1);
}
__device__ __forceinline__ void cpa16(uint32_t dst, const void* src) {
    asm volatile("cp.async.cg.shared.global [%0], [%1], 16;" :: "r"(dst), "l"(src));
}
__device__ __forceinline__ void ldmx4(uint32_t* r, uint32_t addr) {
    asm volatile("ldmatrix.sync.aligned.m8n8.x4.shared.b16 {%0,%1,%2,%3}, [%4];"
                 : "=r"(r[0]), "=r"(r[1]), "=r"(r[2]), "=r"(r[3]) : "r"(addr));
}
__device__ __forceinline__ void mma16816(float* c, const uint32_t* a, const uint32_t* b) {
    asm volatile("mma.sync.aligned.m16n8k16.row.col.f32.bf16.bf16.f32 "
                 "{%0,%1,%2,%3},{%4,%5,%6,%7},{%8,%9},{%0,%1,%2,%3};"
                 : "+f"(c[0]), "+f"(c[1]), "+f"(c[2]), "+f"(c[3])
                 : "r"(a[0]), "r"(a[1]), "r"(a[2]), "r"(a[3]), "r"(b[0]), "r"(b[1]));
}

#define SMEMSZ 81920   // 2 stages * 4 pieces * 128 rows * 80B

// ---------------- prep: split weights ----------------
__global__ void split_w(const float* __restrict__ qw, const float* __restrict__ pw,
                        u16* qh, u16* ql, u16* ph_, u16* pl_) {
    int i = blockIdx.x * 256 + threadIdx.x;
    if (i < 768 * 256) {
        float v = qw[i];
        u16 h = bfbits(v);
        qh[i] = h; ql[i] = bfbits(v - bfval(h));
    } else {
        int j = i - 768 * 256;
        float v = pw[j];
        u16 h = bfbits(v);
        ph_[j] = h; pl_[j] = bfbits(v - bfval(h));
    }
}

// ---------------- GroupNorm -> split transposed xn^T [b][n][c] ----------------
__global__ void __launch_bounds__(256) gn_split(const float* __restrict__ x,
                                                const float* __restrict__ gw,
                                                const float* __restrict__ gb,
                                                u16* __restrict__ xh,
                                                u16* __restrict__ xl) {
    int b = blockIdx.x >> 3, g = blockIdx.x & 7;
    const size_t base = ((size_t)b * C_CH + g * 32) * N_PIX;
    const float* xp = x + base;
    const int TOT = 32 * N_PIX;

    float s = 0.f, s2 = 0.f;
    for (int i = threadIdx.x; i < TOT; i += 256) {
        float v = xp[i]; s += v; s2 += v * v;
    }
    #pragma unroll
    for (int o = 16; o > 0; o >>= 1) {
        s  += __shfl_xor_sync(0xFFFFFFFFu, s,  o);
        s2 += __shfl_xor_sync(0xFFFFFFFFu, s2, o);
    }
    __shared__ float shs[8], shs2[8], s_mean, s_inv, sgw[32], sgb[32];
    int wid = threadIdx.x >> 5, lid = threadIdx.x & 31;
    if (lid == 0) { shs[wid] = s; shs2[wid] = s2; }
    __syncthreads();
    if (threadIdx.x == 0) {
        float ts = 0.f, ts2 = 0.f;
        #pragma unroll
        for (int i = 0; i < 8; i++) { ts += shs[i]; ts2 += shs2[i]; }
        float mean = ts / (float)TOT;
        float var  = ts2 / (float)TOT - mean * mean;
        s_mean = mean; s_inv = rsqrtf(var + 1e-5f);
    }
    if (threadIdx.x < 32) { sgw[threadIdx.x] = gw[g * 32 + threadIdx.x]; sgb[threadIdx.x] = gb[g * 32 + threadIdx.x]; }
    __syncthreads();
    float mean = s_mean, inv = s_inv;

    for (int rep = 0; rep < 16; rep++) {
        int n = threadIdx.x + (rep << 8);
        uint32_t hb[16], lb[16];
        #pragma unroll
        for (int c2 = 0; c2 < 16; c2++) {
            int c = c2 * 2;
            float v0 = (xp[(size_t)c * N_PIX + n]       - mean) * inv * sgw[c]     + sgb[c];
            float v1 = (xp[(size_t)(c + 1) * N_PIX + n] - mean) * inv * sgw[c + 1] + sgb[c + 1];
            split2(v0, v1, hb[c2], lb[c2]);
        }
        size_t di = ((size_t)b * N_PIX + n) * C_CH + g * 32;
        #pragma unroll
        for (int q = 0; q < 4; q++) {
            *(uint4*)(xh + di + q * 8) = make_uint4(hb[q*4], hb[q*4+1], hb[q*4+2], hb[q*4+3]);
            *(uint4*)(xl + di + q * 8) = make_uint4(lb[q*4], lb[q*4+1], lb[q*4+2], lb[q*4+3]);
        }
    }
}

// ---------------- softmax: fp32 S -> split bf16 attn ----------------
__global__ void __launch_bounds__(256) softmax_kernel(const float* __restrict__ S,
                                                      u16* __restrict__ ah,
                                                      u16* __restrict__ al) {
    const float* p = S + (size_t)blockIdx.x * N_PIX;
    u16* ph = ah + (size_t)blockIdx.x * N_PIX;
    u16* pl = al + (size_t)blockIdx.x * N_PIX;
    const int t = threadIdx.x;
    float v[16];
    float mx = -1e30f;
    #pragma unroll
    for (int r = 0; r < 16; r++) { v[r] = p[t + 256 * r]; mx = fmaxf(mx, v[r]); }
    __shared__ float red[8], bval;
    int wid = t >> 5, lid = t & 31;
    #pragma unroll
    for (int o = 16; o > 0; o >>= 1) mx = fmaxf(mx, __shfl_xor_sync(0xFFFFFFFFu, mx, o));
    if (lid == 0) red[wid] = mx;
    __syncthreads();
    if (t == 0) {
        float m = red[0];
        #pragma unroll
        for (int i = 1; i < 8; i++) m = fmaxf(m, red[i]);
        bval = m;
    }
    __syncthreads();
    mx = bval;
    float sum = 0.f;
    #pragma unroll
    for (int r = 0; r < 16; r++) { v[r] = __expf(v[r] - mx); sum += v[r]; }
    #pragma unroll
    for (int o = 16; o > 0; o >>= 1) sum += __shfl_xor_sync(0xFFFFFFFFu, sum, o);
    __syncthreads();
    if (lid == 0) red[wid] = sum;
    __syncthreads();
    if (t == 0) {
        float ssum = 0.f;
        #pragma unroll
        for (int i = 0; i < 8; i++) ssum += red[i];
        bval = 1.0f / ssum;
    }
    __syncthreads();
    float inv = bval;
    #pragma unroll
    for (int r = 0; r < 16; r++) {
        float val = v[r] * inv;
        u16 hi = bfbits(val);
        ph[t + 256 * r] = hi;
        pl[t + 256 * r] = bfbits(val - bfval(hi));
    }
}

// ---------------- chunk loader: 4 pieces of 128x32 bf16, 80B rows ----------------
__device__ __forceinline__ void load_chunk(uint32_t st, int k0,
                                           const u16* Ahb, const u16* Alb,
                                           const u16* Bhb, const u16* Blb,
                                           int lda, int ldb, int tid) {
    #pragma unroll
    for (int it = 0; it < 2; it++) {
        int id = tid + (it << 8);
        int row = id >> 2, kc = id & 3;
        uint32_t off = row * 80 + kc * 16;
        size_t ga = (size_t)row * lda + k0 + kc * 8;
        size_t gb2 = (size_t)row * ldb + k0 + kc * 8;
        cpa16(st + off,         Ahb + ga);
        cpa16(st + 10240 + off, Alb + ga);
        cpa16(st + 20480 + off, Bhb + gb2);
        cpa16(st + 30720 + off, Blb + gb2);
    }
}

// ---------------- split-bf16 mma.sync GEMM ----------------
// D[m,n] = sum_k A(m,k)*B(n,k); 128x128 tile; A/B pre-split bf16 hi/lo, k-major.
// EPI: 0 scores (fp32*alpha), 1 AV (split store), 2 qkv (bias; q/k transposed split, v split),
//      3 proj (bias + resid, fp32)
template <int EPI>
__global__ void __launch_bounds__(256, 1)
gemm_mma(const u16* __restrict__ Ah, const u16* __restrict__ Al, long long sA, int lda,
         const u16* __restrict__ Bh, const u16* __restrict__ Bl, long long sB, int ldb,
         int K, int ldc, long long sOut, float alpha,
         const float* __restrict__ bias, const float* __restrict__ resid,
         float* __restrict__ outF,
         u16* __restrict__ o1h, u16* __restrict__ o1l,
         u16* __restrict__ o2h, u16* __restrict__ o2l,
         u16* __restrict__ o3h, u16* __restrict__ o3l) {
    extern __shared__ __align__(16) char smem[];
    const int tid = threadIdx.x;
    const int wid = tid >> 5, lane = tid & 31;
    const int wm = wid >> 1, wn = wid & 1;
    const int m0 = blockIdx.y * 128, n0 = blockIdx.x * 128, bz = blockIdx.z;

    const u16* Ahb = Ah + sA * bz + (size_t)m0 * lda;
    const u16* Alb = Al + sA * bz + (size_t)m0 * lda;
    const u16* Bhb = Bh + sB * bz + (size_t)n0 * ldb;
    const u16* Blb = Bl + sB * bz + (size_t)n0 * ldb;

    const uint32_t sb = smem_u32(smem);

    float acc[2][8][4] = {};

    // ldmatrix lane address components
    const int ar  = lane & 15;
    const int akb = (lane >> 4) << 4;                       // 0/16 bytes
    const int br  = (lane & 7) + ((lane >> 4) << 3);
    const int bkb = ((lane >> 3) & 1) << 4;
    uint32_t aRow[2], bRow[4];
    #pragma unroll
    for (int mt = 0; mt < 2; mt++) aRow[mt] = (uint32_t)((wm * 32 + mt * 16 + ar) * 80 + akb);
    #pragma unroll
    for (int nt2 = 0; nt2 < 4; nt2++) bRow[nt2] = (uint32_t)((wn * 64 + nt2 * 16 + br) * 80 + bkb);

    load_chunk(sb, 0, Ahb, Alb, Bhb, Blb, lda, ldb, tid);
    asm volatile("cp.async.commit_group;" ::: "memory");

    const int NC = K >> 5;
    for (int c = 0; c < NC; c++) {
        if (c + 1 < NC)
            load_chunk(sb + ((c + 1) & 1) * 40960, (c + 1) << 5, Ahb, Alb, Bhb, Blb, lda, ldb, tid);
        asm volatile("cp.async.commit_group;" ::: "memory");
        asm volatile("cp.async.wait_group 1;" ::: "memory");
        __syncthreads();
        uint32_t st = sb + (c & 1) * 40960;
        #pragma unroll
        for (int ks = 0; ks < 2; ks++) {
            uint32_t a_h[2][4], a_l[2][4], b_h[4][4], b_l[4][4];
            #pragma unroll
            for (int mt = 0; mt < 2; mt++) {
                ldmx4(a_h[mt], st + aRow[mt] + ks * 32);
                ldmx4(a_l[mt], st + 10240 + aRow[mt] + ks * 32);
            }
            #pragma unroll
            for (int nt2 = 0; nt2 < 4; nt2++) {
                ldmx4(b_h[nt2], st + 20480 + bRow[nt2] + ks * 32);
                ldmx4(b_l[nt2], st + 30720 + bRow[nt2] + ks * 32);
            }
            #pragma unroll
            for (int mt = 0; mt < 2; mt++)
                #pragma unroll
                for (int nt = 0; nt < 8; nt++) {
                    const uint32_t* bh2 = &b_h[nt >> 1][(nt & 1) * 2];
                    const uint32_t* bl2 = &b_l[nt >> 1][(nt & 1) * 2];
                    mma16816(acc[mt][nt], a_h[mt], bh2);
                    mma16816(acc[mt][nt], a_h[mt], bl2);
                    mma16816(acc[mt][nt], a_l[mt], bh2);
                }
        }
        __syncthreads();
    }

    const int rB = lane >> 2;
    const int cB = (lane & 3) * 2;

    if (EPI == 0) {
        float* Ob = outF + sOut * bz;
        #pragma unroll
        for (int mt = 0; mt < 2; mt++)
            #pragma unroll
            for (int nt = 0; nt < 8; nt++)
                #pragma unroll
                for (int h = 0; h < 2; h++) {
                    int rowG = m0 + wm * 32 + mt * 16 + rB + h * 8;
                    int colG = n0 + wn * 64 + nt * 8 + cB;
                    float2 v = make_float2(acc[mt][nt][h * 2] * alpha, acc[mt][nt][h * 2 + 1] * alpha);
                    *(float2*)(Ob + (size_t)rowG * ldc + colG) = v;
                }
    } else if (EPI == 1) {
        u16* Oh = o1h + sOut * bz;
        u16* Ol = o1l + sOut * bz;
        #pragma unroll
        for (int mt = 0; mt < 2; mt++)
            #pragma unroll
            for (int nt = 0; nt < 8; nt++)
                #pragma unroll
                for (int h = 0; h < 2; h++) {
                    int rowG = m0 + wm * 32 + mt * 16 + rB + h * 8;
                    int colG = n0 + wn * 64 + nt * 8 + cB;
                    uint32_t hv, lv;
                    split2(acc[mt][nt][h * 2], acc[mt][nt][h * 2 + 1], hv, lv);
                    size_t di = (size_t)rowG * ldc + colG;
                    *(uint32_t*)(Oh + di) = hv;
                    *(uint32_t*)(Ol + di) = lv;
                }
    } else if (EPI == 3) {
        float* Ob = outF + sOut * bz;
        const float* Rb = resid + sOut * bz;
        #pragma unroll
        for (int mt = 0; mt < 2; mt++)
            #pragma unroll
            for (int nt = 0; nt < 8; nt++)
                #pragma unroll
                for (int h = 0; h < 2; h++) {
                    int rowG = m0 + wm * 32 + mt * 16 + rB + h * 8;
                    int colG = n0 + wn * 64 + nt * 8 + cB;
                    float bv = bias[rowG];
                    size_t di = (size_t)rowG * ldc + colG;
                    float2 rv = *(const float2*)(Rb + di);
                    float2 v = make_float2(acc[mt][nt][h * 2] + bv + rv.x,
                                           acc[mt][nt][h * 2 + 1] + bv + rv.y);
                    *(float2*)(Ob + di) = v;
                }
    } else {  // EPI 2: qkv
        int sect = m0 >> 8;
        int msub = m0 & 255;
        if (sect == 2) {   // v: split store [c][4096] + bias
            u16* Vh = o3h + (size_t)1048576 * bz;
            u16* Vl = o3l + (size_t)1048576 * bz;
            #pragma unroll
            for (int mt = 0; mt < 2; mt++)
                #pragma unroll
                for (int nt = 0; nt < 8; nt++)
                    #pragma unroll
                    for (int h = 0; h < 2; h++) {
                        int rowL = wm * 32 + mt * 16 + rB + h * 8;
                        float bv = bias[m0 + rowL];
                        int colG = n0 + wn * 64 + nt * 8 + cB;
                        uint32_t hv, lv;
                        split2(acc[mt][nt][h * 2] + bv, acc[mt][nt][h * 2 + 1] + bv, hv, lv);
                        size_t di = (size_t)(msub + rowL) * N_PIX + colG;
                        *(uint32_t*)(Vh + di) = hv;
                        *(uint32_t*)(Vl + di) = lv;
                    }
        } else {           // q/k: transpose via SMEM bounce -> [n][256]
            u16* Dh = (sect ? o2h : o1h) + (size_t)1048576 * bz;
            u16* Dl = (sect ? o2l : o1l) + (size_t)1048576 * bz;
            float* tsm = (float*)smem;
            #pragma unroll
            for (int mt = 0; mt < 2; mt++)
                #pragma unroll
                for (int h = 0; h < 2; h++) {
                    int rowL = wm * 32 + mt * 16 + rB + h * 8;
                    float bv = bias[m0 + rowL];
                    #pragma unroll
                    for (int nt = 0; nt < 8; nt++) {
                        int colL = wn * 64 + nt * 8 + cB;
                        tsm[rowL * 133 + colL]     = acc[mt][nt][h * 2] + bv;
                        tsm[rowL * 133 + colL + 1] = acc[mt][nt][h * 2 + 1] + bv;
                    }
                }
            __syncthreads();
            #pragma unroll
            for (int it = 0; it < 32; it++) {
                int lin = tid + (it << 8);
                int n  = lin >> 6;
                int op = (lin & 63) << 1;
                float f0 = tsm[op * 133 + n];
                float f1 = tsm[(op + 1) * 133 + n];
                uint32_t hv, lv;
                split2(f0, f1, hv, lv);
                size_t di = (size_t)(n0 + n) * C_CH + msub + op;
                *(uint32_t*)(Dh + di) = hv;
                *(uint32_t*)(Dl + di) = lv;
            }
        }
    }
}

// ---------------- launch ----------------
extern "C" void kernel_launch(void* const* d_in, const int* in_sizes, int n_in,
                              void* d_out, int out_size) {
    const float* x      = (const float*)d_in[0];
    const float* gn_w   = (const float*)d_in[1];
    const float* gn_b   = (const float*)d_in[2];
    const float* qkv_w  = (const float*)d_in[3];
    const float* qkv_b  = (const float*)d_in[4];
    const float* proj_w = (const float*)d_in[5];
    const float* proj_b = (const float*)d_in[6];
    float* out = (float*)d_out;

    u16 *wh, *wl, *ph, *pl, *xnh, *xnl, *qTh, *qTl, *kTh, *kTl, *vh, *vl, *ah, *al, *oh, *ol;
    float* S;
    cudaGetSymbolAddress((void**)&wh, g_wh);   cudaGetSymbolAddress((void**)&wl, g_wl);
    cudaGetSymbolAddress((void**)&ph, g_ph);   cudaGetSymbolAddress((void**)&pl, g_pl);
    cudaGetSymbolAddress((void**)&xnh, g_xnh); cudaGetSymbolAddress((void**)&xnl, g_xnl);
    cudaGetSymbolAddress((void**)&qTh, g_qTh); cudaGetSymbolAddress((void**)&qTl, g_qTl);
    cudaGetSymbolAddress((void**)&kTh, g_kTh); cudaGetSymbolAddress((void**)&kTl, g_kTl);
    cudaGetSymbolAddress((void**)&vh, g_vh);   cudaGetSymbolAddress((void**)&vl, g_vl);
    cudaGetSymbolAddress((void**)&ah, g_ah);   cudaGetSymbolAddress((void**)&al, g_al);
    cudaGetSymbolAddress((void**)&oh, g_oh);   cudaGetSymbolAddress((void**)&ol, g_ol);
    cudaGetSymbolAddress((void**)&S, g_S);

    cudaFuncSetAttribute(gemm_mma<0>, cudaFuncAttributeMaxDynamicSharedMemorySize, SMEMSZ);
    cudaFuncSetAttribute(gemm_mma<1>, cudaFuncAttributeMaxDynamicSharedMemorySize, SMEMSZ);
    cudaFuncSetAttribute(gemm_mma<2>, cudaFuncAttributeMaxDynamicSharedMemorySize, SMEMSZ);
    cudaFuncSetAttribute(gemm_mma<3>, cudaFuncAttributeMaxDynamicSharedMemorySize, SMEMSZ);

    const long long sNC  = (long long)N_PIX * C_CH;      // 1M
    const long long sATT = (long long)N_PIX * N_PIX;     // 16M

    // 0) split weights
    split_w<<<1024, 256>>>(qkv_w, proj_w, wh, wl, ph, pl);

    // 1) GroupNorm -> xn^T hi/lo
    gn_split<<<64, 256>>>(x, gn_w, gn_b, xnh, xnl);

    // 2) QKV: D[o,n] = sum_c W[o,c] xnT[n,c]; -> qT/kT (transposed split), v (split)
    gemm_mma<2><<<dim3(32, 6, B_SZ), 256, SMEMSZ>>>(
        wh, wl, 0, C_CH, xnh, xnl, sNC, C_CH, C_CH, 0, 0, 1.0f,
        qkv_b, nullptr, nullptr, qTh, qTl, kTh, kTl, vh, vl);

    // 3) scores: S[i,j] = (1/16) sum_c qT[i,c] kT[j,c]
    gemm_mma<0><<<dim3(32, 32, B_SZ), 256, SMEMSZ>>>(
        qTh, qTl, sNC, C_CH, kTh, kTl, sNC, C_CH, C_CH, N_PIX, sATT, 0.0625f,
        nullptr, nullptr, S, nullptr, nullptr, nullptr, nullptr, nullptr, nullptr);

    // 4) softmax -> attn hi/lo
    softmax_kernel<<<B_SZ * N_PIX, 256>>>(S, ah, al);

    // 5) AV: O[i,c] = sum_m attn[i,m] v[c,m] -> split store [i][c]
    gemm_mma<1><<<dim3(2, 32, B_SZ), 256, SMEMSZ>>>(
        ah, al, sATT, N_PIX, vh, vl, sNC, N_PIX, N_PIX, C_CH, sNC, 1.0f,
        nullptr, nullptr, nullptr, oh, ol, nullptr, nullptr, nullptr, nullptr);

    // 6) proj: out[o,i] = sum_c P[o,c] O[i,c] + pb[o] + x
    gemm_mma<3><<<dim3(32, 2, B_SZ), 256, SMEMSZ>>>(
        ph, pl, 0, C_CH, oh, ol, sNC, C_CH, C_CH, N_PIX, sNC, 1.0f,
        proj_b, x, out, nullptr, nullptr, nullptr, nullptr, nullptr, nullptr);
}

// round 4
// speedup vs baseline: 2.9644x; 1.2131x over previous
#include <cuda_runtime.h>
#include <cuda_bf16.h>
#include <cstdint>

#define B_SZ  8
#define C_CH  256
#define N_PIX 4096

typedef unsigned short u16;

// ---------------- scratch (device globals) ----------------
__device__ u16 g_wh[768 * 256],  g_wl[768 * 256];
__device__ u16 g_ph[256 * 256],  g_pl[256 * 256];
__device__ u16 g_xnh[B_SZ * N_PIX * C_CH], g_xnl[B_SZ * N_PIX * C_CH];   // xn^T [b][n][c]
__device__ u16 g_qTh[B_SZ * N_PIX * C_CH], g_qTl[B_SZ * N_PIX * C_CH];
__device__ u16 g_kTh[B_SZ * N_PIX * C_CH], g_kTl[B_SZ * N_PIX * C_CH];
__device__ u16 g_vh [B_SZ * C_CH * N_PIX], g_vl [B_SZ * C_CH * N_PIX];   // v [b][c][m]
__device__ float g_S[(size_t)B_SZ * N_PIX * N_PIX];                      // 512MB
__device__ u16 g_ah[(size_t)B_SZ * N_PIX * N_PIX];                       // 256MB
__device__ u16 g_al[(size_t)B_SZ * N_PIX * N_PIX];                       // 256MB
__device__ u16 g_oh[B_SZ * N_PIX * C_CH], g_ol[B_SZ * N_PIX * C_CH];     // O [b][i][c]

// ---------------- helpers ----------------
__device__ __forceinline__ uint32_t smem_u32(const void* p) {
    uint32_t a;
    asm("{ .reg .u64 t; cvta.to.shared.u64 t, %1; cvt.u32.u64 %0, t; }" : "=r"(a) : "l"(p));
    return a;
}
__device__ __forceinline__ u16 bfbits(float v) {
    return __bfloat16_as_ushort(__float2bfloat16_rn(v));
}
__device__ __forceinline__ float bfval(u16 u) { return __uint_as_float(((uint32_t)u) << 16); }
__device__ __forceinline__ uint32_t pk(u16 a, u16 b) { return (uint32_t)a | ((uint32_t)b << 16); }
__device__ __forceinline__ void split2(float f0, float f1, uint32_t& h, uint32_t& l) {
    u16 h0 = bfbits(f0), h1 = bfbits(f1);
    u16 l0 = bfbits(f0 - bfval(h0)), l1 = bfbits(f1 - bfval(h1));
    h = pk(h0, h1); l = pk(l0, l1);
}
__device__ __forceinline__ void cpa16(uint32_t dst, const void* src) {
    asm volatile("cp.async.cg.shared.global [%0], [%1], 16;" :: "r"(dst), "l"(src));
}
__device__ __forceinline__ void ldmx4(uint32_t* r, uint32_t addr) {
    asm volatile("ldmatrix.sync.aligned.m8n8.x4.shared.b16 {%0,%1,%2,%3}, [%4];"
                 : "=r"(r[0]), "=r"(r[1]), "=r"(r[2]), "=r"(r[3]) : "r"(addr));
}
__device__ __forceinline__ void mma16816(float* c, const uint32_t* a, const uint32_t* b) {
    asm volatile("mma.sync.aligned.m16n8k16.row.col.f32.bf16.bf16.f32 "
                 "{%0,%1,%2,%3},{%4,%5,%6,%7},{%8,%9},{%0,%1,%2,%3};"
                 : "+f"(c[0]), "+f"(c[1]), "+f"(c[2]), "+f"(c[3])
                 : "r"(a[0]), "r"(a[1]), "r"(a[2]), "r"(a[3]), "r"(b[0]), "r"(b[1]));
}

#define SMEMSZ 81920   // 2 stages * 4 pieces * 128 rows * 80B

// ---------------- prep: split weights ----------------
__global__ void split_w(const float* __restrict__ qw, const float* __restrict__ pw,
                        u16* qh, u16* ql, u16* ph_, u16* pl_) {
    int i = blockIdx.x * 256 + threadIdx.x;
    if (i < 768 * 256) {
        float v = qw[i];
        u16 h = bfbits(v);
        qh[i] = h; ql[i] = bfbits(v - bfval(h));
    } else {
        int j = i - 768 * 256;
        float v = pw[j];
        u16 h = bfbits(v);
        ph_[j] = h; pl_[j] = bfbits(v - bfval(h));
    }
}

// ---------------- GroupNorm -> split transposed xn^T [b][n][c] ----------------
__global__ void __launch_bounds__(256) gn_split(const float* __restrict__ x,
                                                const float* __restrict__ gw,
                                                const float* __restrict__ gb,
                                                u16* __restrict__ xh,
                                                u16* __restrict__ xl) {
    int b = blockIdx.x >> 3, g = blockIdx.x & 7;
    const size_t base = ((size_t)b * C_CH + g * 32) * N_PIX;
    const float* xp = x + base;
    const int TOT = 32 * N_PIX;

    float s = 0.f, s2 = 0.f;
    for (int i = threadIdx.x; i < TOT; i += 256) {
        float v = xp[i]; s += v; s2 += v * v;
    }
    #pragma unroll
    for (int o = 16; o > 0; o >>= 1) {
        s  += __shfl_xor_sync(0xFFFFFFFFu, s,  o);
        s2 += __shfl_xor_sync(0xFFFFFFFFu, s2, o);
    }
    __shared__ float shs[8], shs2[8], s_mean, s_inv, sgw[32], sgb[32];
    int wid = threadIdx.x >> 5, lid = threadIdx.x & 31;
    if (lid == 0) { shs[wid] = s; shs2[wid] = s2; }
    __syncthreads();
    if (threadIdx.x == 0) {
        float ts = 0.f, ts2 = 0.f;
        #pragma unroll
        for (int i = 0; i < 8; i++) { ts += shs[i]; ts2 += shs2[i]; }
        float mean = ts / (float)TOT;
        float var  = ts2 / (float)TOT - mean * mean;
        s_mean = mean; s_inv = rsqrtf(var + 1e-5f);
    }
    if (threadIdx.x < 32) { sgw[threadIdx.x] = gw[g * 32 + threadIdx.x]; sgb[threadIdx.x] = gb[g * 32 + threadIdx.x]; }
    __syncthreads();
    float mean = s_mean, inv = s_inv;

    for (int rep = 0; rep < 16; rep++) {
        int n = threadIdx.x + (rep << 8);
        uint32_t hb[16], lb[16];
        #pragma unroll
        for (int c2 = 0; c2 < 16; c2++) {
            int c = c2 * 2;
            float v0 = (xp[(size_t)c * N_PIX + n]       - mean) * inv * sgw[c]     + sgb[c];
            float v1 = (xp[(size_t)(c + 1) * N_PIX + n] - mean) * inv * sgw[c + 1] + sgb[c + 1];
            split2(v0, v1, hb[c2], lb[c2]);
        }
        size_t di = ((size_t)b * N_PIX + n) * C_CH + g * 32;
        #pragma unroll
        for (int q = 0; q < 4; q++) {
            *(uint4*)(xh + di + q * 8) = make_uint4(hb[q*4], hb[q*4+1], hb[q*4+2], hb[q*4+3]);
            *(uint4*)(xl + di + q * 8) = make_uint4(lb[q*4], lb[q*4+1], lb[q*4+2], lb[q*4+3]);
        }
    }
}

// ---------------- softmax: fp32 S -> split bf16 attn ----------------
__global__ void __launch_bounds__(256) softmax_kernel(const float* __restrict__ S,
                                                      u16* __restrict__ ah,
                                                      u16* __restrict__ al) {
    const float* p = S + (size_t)blockIdx.x * N_PIX;
    u16* ph = ah + (size_t)blockIdx.x * N_PIX;
    u16* pl = al + (size_t)blockIdx.x * N_PIX;
    const int t = threadIdx.x;
    float v[16];
    float mx = -1e30f;
    #pragma unroll
    for (int r = 0; r < 16; r++) { v[r] = p[t + 256 * r]; mx = fmaxf(mx, v[r]); }
    __shared__ float red[8], bval;
    int wid = t >> 5, lid = t & 31;
    #pragma unroll
    for (int o = 16; o > 0; o >>= 1) mx = fmaxf(mx, __shfl_xor_sync(0xFFFFFFFFu, mx, o));
    if (lid == 0) red[wid] = mx;
    __syncthreads();
    if (t == 0) {
        float m = red[0];
        #pragma unroll
        for (int i = 1; i < 8; i++) m = fmaxf(m, red[i]);
        bval = m;
    }
    __syncthreads();
    mx = bval;
    float sum = 0.f;
    #pragma unroll
    for (int r = 0; r < 16; r++) { v[r] = __expf(v[r] - mx); sum += v[r]; }
    #pragma unroll
    for (int o = 16; o > 0; o >>= 1) sum += __shfl_xor_sync(0xFFFFFFFFu, sum, o);
    __syncthreads();
    if (lid == 0) red[wid] = sum;
    __syncthreads();
    if (t == 0) {
        float ssum = 0.f;
        #pragma unroll
        for (int i = 0; i < 8; i++) ssum += red[i];
        bval = 1.0f / ssum;
    }
    __syncthreads();
    float inv = bval;
    #pragma unroll
    for (int r = 0; r < 16; r++) {
        float val = v[r] * inv;
        u16 hi = bfbits(val);
        ph[t + 256 * r] = hi;
        pl[t + 256 * r] = bfbits(val - bfval(hi));
    }
}

// ---------------- chunk loader: 4 pieces of 128x32 bf16, 80B rows ----------------
__device__ __forceinline__ void load_chunk(uint32_t st, int k0,
                                           const u16* Ahb, const u16* Alb,
                                           const u16* Bhb, const u16* Blb,
                                           int lda, int ldb, int tid) {
    #pragma unroll
    for (int it = 0; it < 2; it++) {
        int id = tid + (it << 8);
        int row = id >> 2, kc = id & 3;
        uint32_t off = row * 80 + kc * 16;
        size_t ga = (size_t)row * lda + k0 + kc * 8;
        size_t gb2 = (size_t)row * ldb + k0 + kc * 8;
        cpa16(st + off,         Ahb + ga);
        cpa16(st + 10240 + off, Alb + ga);
        cpa16(st + 20480 + off, Bhb + gb2);
        cpa16(st + 30720 + off, Blb + gb2);
    }
}

// ---------------- split-bf16 mma.sync GEMM ----------------
// D[m,n] = sum_k A(m,k)*B(n,k); 128x128 tile; A/B pre-split bf16 hi/lo, k-major.
// EPI: 0 scores (fp32*alpha), 1 AV (split store), 2 qkv (bias; q/k transposed split, v split),
//      3 proj (bias + resid, fp32)
template <int EPI>
__global__ void __launch_bounds__(256, 2)
gemm_mma(const u16* __restrict__ Ah, const u16* __restrict__ Al, long long sA, int lda,
         const u16* __restrict__ Bh, const u16* __restrict__ Bl, long long sB, int ldb,
         int K, int ldc, long long sOut, float alpha,
         const float* __restrict__ bias, const float* __restrict__ resid,
         float* __restrict__ outF,
         u16* __restrict__ o1h, u16* __restrict__ o1l,
         u16* __restrict__ o2h, u16* __restrict__ o2l,
         u16* __restrict__ o3h, u16* __restrict__ o3l) {
    extern __shared__ __align__(16) char smem[];
    const int tid = threadIdx.x;
    const int wid = tid >> 5, lane = tid & 31;
    const int wm = wid >> 1, wn = wid & 1;
    const int m0 = blockIdx.y * 128, n0 = blockIdx.x * 128, bz = blockIdx.z;

    const u16* Ahb = Ah + sA * bz + (size_t)m0 * lda;
    const u16* Alb = Al + sA * bz + (size_t)m0 * lda;
    const u16* Bhb = Bh + sB * bz + (size_t)n0 * ldb;
    const u16* Blb = Bl + sB * bz + (size_t)n0 * ldb;

    const uint32_t sb = smem_u32(smem);

    float acc[2][8][4] = {};

    // ldmatrix lane address components
    const int ar  = lane & 15;
    const int akb = (lane >> 4) << 4;                       // 0/16 bytes
    const int br  = (lane & 7) + ((lane >> 4) << 3);
    const int bkb = ((lane >> 3) & 1) << 4;
    uint32_t aRow[2], bRow[4];
    #pragma unroll
    for (int mt = 0; mt < 2; mt++) aRow[mt] = (uint32_t)((wm * 32 + mt * 16 + ar) * 80 + akb);
    #pragma unroll
    for (int nt2 = 0; nt2 < 4; nt2++) bRow[nt2] = (uint32_t)((wn * 64 + nt2 * 16 + br) * 80 + bkb);

    load_chunk(sb, 0, Ahb, Alb, Bhb, Blb, lda, ldb, tid);
    asm volatile("cp.async.commit_group;" ::: "memory");

    const int NC = K >> 5;
    for (int c = 0; c < NC; c++) {
        if (c + 1 < NC)
            load_chunk(sb + ((c + 1) & 1) * 40960, (c + 1) << 5, Ahb, Alb, Bhb, Blb, lda, ldb, tid);
        asm volatile("cp.async.commit_group;" ::: "memory");
        asm volatile("cp.async.wait_group 1;" ::: "memory");
        __syncthreads();
        uint32_t st = sb + (c & 1) * 40960;
        #pragma unroll
        for (int ks = 0; ks < 2; ks++) {
            uint32_t a_h[2][4], a_l[2][4];
            #pragma unroll
            for (int mt = 0; mt < 2; mt++) {
                ldmx4(a_h[mt], st + aRow[mt] + ks * 32);
                ldmx4(a_l[mt], st + 10240 + aRow[mt] + ks * 32);
            }
            #pragma unroll
            for (int nt2 = 0; nt2 < 4; nt2++) {
                uint32_t b_h[4], b_l[4];
                ldmx4(b_h, st + 20480 + bRow[nt2] + ks * 32);
                ldmx4(b_l, st + 30720 + bRow[nt2] + ks * 32);
                // term-major ordering: 4 independent acc chains per term
                #pragma unroll
                for (int mt = 0; mt < 2; mt++) {
                    mma16816(acc[mt][nt2 * 2],     a_h[mt], b_h);
                    mma16816(acc[mt][nt2 * 2 + 1], a_h[mt], b_h + 2);
                }
                #pragma unroll
                for (int mt = 0; mt < 2; mt++) {
                    mma16816(acc[mt][nt2 * 2],     a_h[mt], b_l);
                    mma16816(acc[mt][nt2 * 2 + 1], a_h[mt], b_l + 2);
                }
                #pragma unroll
                for (int mt = 0; mt < 2; mt++) {
                    mma16816(acc[mt][nt2 * 2],     a_l[mt], b_h);
                    mma16816(acc[mt][nt2 * 2 + 1], a_l[mt], b_h + 2);
                }
            }
        }
        __syncthreads();
    }

    const int rB = lane >> 2;
    const int cB = (lane & 3) * 2;

    if (EPI == 0) {
        float* Ob = outF + sOut * bz;
        #pragma unroll
        for (int mt = 0; mt < 2; mt++)
            #pragma unroll
            for (int nt = 0; nt < 8; nt++)
                #pragma unroll
                for (int h = 0; h < 2; h++) {
                    int rowG = m0 + wm * 32 + mt * 16 + rB + h * 8;
                    int colG = n0 + wn * 64 + nt * 8 + cB;
                    float2 v = make_float2(acc[mt][nt][h * 2] * alpha, acc[mt][nt][h * 2 + 1] * alpha);
                    *(float2*)(Ob + (size_t)rowG * ldc + colG) = v;
                }
    } else if (EPI == 1) {
        u16* Oh = o1h + sOut * bz;
        u16* Ol = o1l + sOut * bz;
        #pragma unroll
        for (int mt = 0; mt < 2; mt++)
            #pragma unroll
            for (int nt = 0; nt < 8; nt++)
                #pragma unroll
                for (int h = 0; h < 2; h++) {
                    int rowG = m0 + wm * 32 + mt * 16 + rB + h * 8;
                    int colG = n0 + wn * 64 + nt * 8 + cB;
                    uint32_t hv, lv;
                    split2(acc[mt][nt][h * 2], acc[mt][nt][h * 2 + 1], hv, lv);
                    size_t di = (size_t)rowG * ldc + colG;
                    *(uint32_t*)(Oh + di) = hv;
                    *(uint32_t*)(Ol + di) = lv;
                }
    } else if (EPI == 3) {
        float* Ob = outF + sOut * bz;
        const float* Rb = resid + sOut * bz;
        #pragma unroll
        for (int mt = 0; mt < 2; mt++)
            #pragma unroll
            for (int nt = 0; nt < 8; nt++)
                #pragma unroll
                for (int h = 0; h < 2; h++) {
                    int rowG = m0 + wm * 32 + mt * 16 + rB + h * 8;
                    int colG = n0 + wn * 64 + nt * 8 + cB;
                    float bv = bias[rowG];
                    size_t di = (size_t)rowG * ldc + colG;
                    float2 rv = *(const float2*)(Rb + di);
                    float2 v = make_float2(acc[mt][nt][h * 2] + bv + rv.x,
                                           acc[mt][nt][h * 2 + 1] + bv + rv.y);
                    *(float2*)(Ob + di) = v;
                }
    } else {  // EPI 2: qkv
        int sect = m0 >> 8;
        int msub = m0 & 255;
        if (sect == 2) {   // v: split store [c][4096] + bias
            u16* Vh = o3h + (size_t)1048576 * bz;
            u16* Vl = o3l + (size_t)1048576 * bz;
            #pragma unroll
            for (int mt = 0; mt < 2; mt++)
                #pragma unroll
                for (int nt = 0; nt < 8; nt++)
                    #pragma unroll
                    for (int h = 0; h < 2; h++) {
                        int rowL = wm * 32 + mt * 16 + rB + h * 8;
                        float bv = bias[m0 + rowL];
                        int colG = n0 + wn * 64 + nt * 8 + cB;
                        uint32_t hv, lv;
                        split2(acc[mt][nt][h * 2] + bv, acc[mt][nt][h * 2 + 1] + bv, hv, lv);
                        size_t di = (size_t)(msub + rowL) * N_PIX + colG;
                        *(uint32_t*)(Vh + di) = hv;
                        *(uint32_t*)(Vl + di) = lv;
                    }
        } else {           // q/k: transpose via SMEM bounce -> [n][256]
            u16* Dh = (sect ? o2h : o1h) + (size_t)1048576 * bz;
            u16* Dl = (sect ? o2l : o1l) + (size_t)1048576 * bz;
            float* tsm = (float*)smem;
            #pragma unroll
            for (int mt = 0; mt < 2; mt++)
                #pragma unroll
                for (int h = 0; h < 2; h++) {
                    int rowL = wm * 32 + mt * 16 + rB + h * 8;
                    float bv = bias[m0 + rowL];
                    #pragma unroll
                    for (int nt = 0; nt < 8; nt++) {
                        int colL = wn * 64 + nt * 8 + cB;
                        tsm[rowL * 133 + colL]     = acc[mt][nt][h * 2] + bv;
                        tsm[rowL * 133 + colL + 1] = acc[mt][nt][h * 2 + 1] + bv;
                    }
                }
            __syncthreads();
            #pragma unroll
            for (int it = 0; it < 32; it++) {
                int lin = tid + (it << 8);
                int n  = lin >> 6;
                int op = (lin & 63) << 1;
                float f0 = tsm[op * 133 + n];
                float f1 = tsm[(op + 1) * 133 + n];
                uint32_t hv, lv;
                split2(f0, f1, hv, lv);
                size_t di = (size_t)(n0 + n) * C_CH + msub + op;
                *(uint32_t*)(Dh + di) = hv;
                *(uint32_t*)(Dl + di) = lv;
            }
        }
    }
}

// ---------------- launch ----------------
extern "C" void kernel_launch(void* const* d_in, const int* in_sizes, int n_in,
                              void* d_out, int out_size) {
    const float* x      = (const float*)d_in[0];
    const float* gn_w   = (const float*)d_in[1];
    const float* gn_b   = (const float*)d_in[2];
    const float* qkv_w  = (const float*)d_in[3];
    const float* qkv_b  = (const float*)d_in[4];
    const float* proj_w = (const float*)d_in[5];
    const float* proj_b = (const float*)d_in[6];
    float* out = (float*)d_out;

    u16 *wh, *wl, *ph, *pl, *xnh, *xnl, *qTh, *qTl, *kTh, *kTl, *vh, *vl, *ah, *al, *oh, *ol;
    float* S;
    cudaGetSymbolAddress((void**)&wh, g_wh);   cudaGetSymbolAddress((void**)&wl, g_wl);
    cudaGetSymbolAddress((void**)&ph, g_ph);   cudaGetSymbolAddress((void**)&pl, g_pl);
    cudaGetSymbolAddress((void**)&xnh, g_xnh); cudaGetSymbolAddress((void**)&xnl, g_xnl);
    cudaGetSymbolAddress((void**)&qTh, g_qTh); cudaGetSymbolAddress((void**)&qTl, g_qTl);
    cudaGetSymbolAddress((void**)&kTh, g_kTh); cudaGetSymbolAddress((void**)&kTl, g_kTl);
    cudaGetSymbolAddress((void**)&vh, g_vh);   cudaGetSymbolAddress((void**)&vl, g_vl);
    cudaGetSymbolAddress((void**)&ah, g_ah);   cudaGetSymbolAddress((void**)&al, g_al);
    cudaGetSymbolAddress((void**)&oh, g_oh);   cudaGetSymbolAddress((void**)&ol, g_ol);
    cudaGetSymbolAddress((void**)&S, g_S);

    cudaFuncSetAttribute(gemm_mma<0>, cudaFuncAttributeMaxDynamicSharedMemorySize, SMEMSZ);
    cudaFuncSetAttribute(gemm_mma<1>, cudaFuncAttributeMaxDynamicSharedMemorySize, SMEMSZ);
    cudaFuncSetAttribute(gemm_mma<2>, cudaFuncAttributeMaxDynamicSharedMemorySize, SMEMSZ);
    cudaFuncSetAttribute(gemm_mma<3>, cudaFuncAttributeMaxDynamicSharedMemorySize, SMEMSZ);

    const long long sNC  = (long long)N_PIX * C_CH;      // 1M
    const long long sATT = (long long)N_PIX * N_PIX;     // 16M

    // 0) split weights
    split_w<<<1024, 256>>>(qkv_w, proj_w, wh, wl, ph, pl);

    // 1) GroupNorm -> xn^T hi/lo
    gn_split<<<64, 256>>>(x, gn_w, gn_b, xnh, xnl);

    // 2) QKV: D[o,n] = sum_c W[o,c] xnT[n,c]; -> qT/kT (transposed split), v (split)
    gemm_mma<2><<<dim3(32, 6, B_SZ), 256, SMEMSZ>>>(
        wh, wl, 0, C_CH, xnh, xnl, sNC, C_CH, C_CH, 0, 0, 1.0f,
        qkv_b, nullptr, nullptr, qTh, qTl, kTh, kTl, vh, vl);

    // 3) scores: S[i,j] = (1/16) sum_c qT[i,c] kT[j,c]
    gemm_mma<0><<<dim3(32, 32, B_SZ), 256, SMEMSZ>>>(
        qTh, qTl, sNC, C_CH, kTh, kTl, sNC, C_CH, C_CH, N_PIX, sATT, 0.0625f,
        nullptr, nullptr, S, nullptr, nullptr, nullptr, nullptr, nullptr, nullptr);

    // 4) softmax -> attn hi/lo
    softmax_kernel<<<B_SZ * N_PIX, 256>>>(S, ah, al);

    // 5) AV: O[i,c] = sum_m attn[i,m] v[c,m] -> split store [i][c]
    gemm_mma<1><<<dim3(2, 32, B_SZ), 256, SMEMSZ>>>(
        ah, al, sATT, N_PIX, vh, vl, sNC, N_PIX, N_PIX, C_CH, sNC, 1.0f,
        nullptr, nullptr, nullptr, oh, ol, nullptr, nullptr, nullptr, nullptr);

    // 6) proj: out[o,i] = sum_c P[o,c] O[i,c] + pb[o] + x
    gemm_mma<3><<<dim3(32, 2, B_SZ), 256, SMEMSZ>>>(
        ph, pl, 0, C_CH, oh, ol, sNC, C_CH, C_CH, N_PIX, sNC, 1.0f,
        proj_b, x, out, nullptr, nullptr, nullptr, nullptr, nullptr, nullptr);
}

// round 5
// speedup vs baseline: 3.0203x; 1.0188x over previous
#include <cuda_runtime.h>
#include <cuda_bf16.h>
#include <cstdint>

#define B_SZ  8
#define C_CH  256
#define N_PIX 4096

typedef unsigned short u16;

// ---------------- scratch (device globals) ----------------
__device__ u16 g_wh[768 * 256],  g_wl[768 * 256];
__device__ u16 g_ph[256 * 256],  g_pl[256 * 256];
__device__ u16 g_xnh[B_SZ * N_PIX * C_CH], g_xnl[B_SZ * N_PIX * C_CH];   // xn^T [b][n][c]
__device__ u16 g_qTh[B_SZ * N_PIX * C_CH], g_qTl[B_SZ * N_PIX * C_CH];
__device__ u16 g_kTh[B_SZ * N_PIX * C_CH], g_kTl[B_SZ * N_PIX * C_CH];
__device__ u16 g_vh [B_SZ * C_CH * N_PIX], g_vl [B_SZ * C_CH * N_PIX];   // v [b][c][m]
__device__ u16 g_ah[(size_t)B_SZ * N_PIX * N_PIX];                       // P~ hi (256MB)
__device__ u16 g_al[(size_t)B_SZ * N_PIX * N_PIX];                       // P~ lo (256MB)
__device__ float g_part[(size_t)B_SZ * N_PIX * 64];                      // row partial sums (8MB)
__device__ float g_rsum[B_SZ * N_PIX];                                   // reciprocal row sums
__device__ u16 g_oh[B_SZ * N_PIX * C_CH], g_ol[B_SZ * N_PIX * C_CH];     // O [b][i][c]

// ---------------- helpers ----------------
__device__ __forceinline__ uint32_t smem_u32(const void* p) {
    uint32_t a;
    asm("{ .reg .u64 t; cvta.to.shared.u64 t, %1; cvt.u32.u64 %0, t; }" : "=r"(a) : "l"(p));
    return a;
}
__device__ __forceinline__ u16 bfbits(float v) {
    return __bfloat16_as_ushort(__float2bfloat16_rn(v));
}
__device__ __forceinline__ float bfval(u16 u) { return __uint_as_float(((uint32_t)u) << 16); }
__device__ __forceinline__ uint32_t pk(u16 a, u16 b) { return (uint32_t)a | ((uint32_t)b << 16); }
__device__ __forceinline__ void split2(float f0, float f1, uint32_t& h, uint32_t& l) {
    u16 h0 = bfbits(f0), h1 = bfbits(f1);
    u16 l0 = bfbits(f0 - bfval(h0)), l1 = bfbits(f1 - bfval(h1));
    h = pk(h0, h1); l = pk(l0, l1);
}
__device__ __forceinline__ void cpa16(uint32_t dst, const void* src) {
    asm volatile("cp.async.cg.shared.global [%0], [%1], 16;" :: "r"(dst), "l"(src));
}
__device__ __forceinline__ void ldmx4(uint32_t* r, uint32_t addr) {
    asm volatile("ldmatrix.sync.aligned.m8n8.x4.shared.b16 {%0,%1,%2,%3}, [%4];"
                 : "=r"(r[0]), "=r"(r[1]), "=r"(r[2]), "=r"(r[3]) : "r"(addr));
}
__device__ __forceinline__ void mma16816(float* c, const uint32_t* a, const uint32_t* b) {
    asm volatile("mma.sync.aligned.m16n8k16.row.col.f32.bf16.bf16.f32 "
                 "{%0,%1,%2,%3},{%4,%5,%6,%7},{%8,%9},{%0,%1,%2,%3};"
                 : "+f"(c[0]), "+f"(c[1]), "+f"(c[2]), "+f"(c[3])
                 : "r"(a[0]), "r"(a[1]), "r"(a[2]), "r"(a[3]), "r"(b[0]), "r"(b[1]));
}

#define SMEMSZ 81920   // 2 stages * 4 pieces * 128 rows * 80B

// ---------------- prep: split weights ----------------
__global__ void split_w(const float* __restrict__ qw, const float* __restrict__ pw,
                        u16* qh, u16* ql, u16* ph_, u16* pl_) {
    int i = blockIdx.x * 256 + threadIdx.x;
    if (i < 768 * 256) {
        float v = qw[i];
        u16 h = bfbits(v);
        qh[i] = h; ql[i] = bfbits(v - bfval(h));
    } else {
        int j = i - 768 * 256;
        float v = pw[j];
        u16 h = bfbits(v);
        ph_[j] = h; pl_[j] = bfbits(v - bfval(h));
    }
}

// ---------------- GroupNorm -> split transposed xn^T [b][n][c] ----------------
__global__ void __launch_bounds__(256) gn_split(const float* __restrict__ x,
                                                const float* __restrict__ gw,
                                                const float* __restrict__ gb,
                                                u16* __restrict__ xh,
                                                u16* __restrict__ xl) {
    int b = blockIdx.x >> 3, g = blockIdx.x & 7;
    const size_t base = ((size_t)b * C_CH + g * 32) * N_PIX;
    const float* xp = x + base;
    const int TOT = 32 * N_PIX;

    float s = 0.f, s2 = 0.f;
    for (int i = threadIdx.x; i < TOT; i += 256) {
        float v = xp[i]; s += v; s2 += v * v;
    }
    #pragma unroll
    for (int o = 16; o > 0; o >>= 1) {
        s  += __shfl_xor_sync(0xFFFFFFFFu, s,  o);
        s2 += __shfl_xor_sync(0xFFFFFFFFu, s2, o);
    }
    __shared__ float shs[8], shs2[8], s_mean, s_inv, sgw[32], sgb[32];
    int wid = threadIdx.x >> 5, lid = threadIdx.x & 31;
    if (lid == 0) { shs[wid] = s; shs2[wid] = s2; }
    __syncthreads();
    if (threadIdx.x == 0) {
        float ts = 0.f, ts2 = 0.f;
        #pragma unroll
        for (int i = 0; i < 8; i++) { ts += shs[i]; ts2 += shs2[i]; }
        float mean = ts / (float)TOT;
        float var  = ts2 / (float)TOT - mean * mean;
        s_mean = mean; s_inv = rsqrtf(var + 1e-5f);
    }
    if (threadIdx.x < 32) { sgw[threadIdx.x] = gw[g * 32 + threadIdx.x]; sgb[threadIdx.x] = gb[g * 32 + threadIdx.x]; }
    __syncthreads();
    float mean = s_mean, inv = s_inv;

    for (int rep = 0; rep < 16; rep++) {
        int n = threadIdx.x + (rep << 8);
        uint32_t hb[16], lb[16];
        #pragma unroll
        for (int c2 = 0; c2 < 16; c2++) {
            int c = c2 * 2;
            float v0 = (xp[(size_t)c * N_PIX + n]       - mean) * inv * sgw[c]     + sgb[c];
            float v1 = (xp[(size_t)(c + 1) * N_PIX + n] - mean) * inv * sgw[c + 1] + sgb[c + 1];
            split2(v0, v1, hb[c2], lb[c2]);
        }
        size_t di = ((size_t)b * N_PIX + n) * C_CH + g * 32;
        #pragma unroll
        for (int q = 0; q < 4; q++) {
            *(uint4*)(xh + di + q * 8) = make_uint4(hb[q*4], hb[q*4+1], hb[q*4+2], hb[q*4+3]);
            *(uint4*)(xl + di + q * 8) = make_uint4(lb[q*4], lb[q*4+1], lb[q*4+2], lb[q*4+3]);
        }
    }
}

// ---------------- rowsum reduce: partials[64] -> 1/sum, one warp per row ----------------
__global__ void __launch_bounds__(256) rowsum_reduce(const float* __restrict__ part,
                                                     float* __restrict__ rsum) {
    int gw = (blockIdx.x * 256 + threadIdx.x) >> 5;
    int lane = threadIdx.x & 31;
    const float* p = part + (size_t)gw * 64;
    float s = p[lane] + p[lane + 32];
    #pragma unroll
    for (int o = 16; o > 0; o >>= 1) s += __shfl_xor_sync(0xFFFFFFFFu, s, o);
    if (lane == 0) rsum[gw] = 1.0f / s;
}

// ---------------- chunk loader: 4 pieces of 128x32 bf16, 80B rows ----------------
__device__ __forceinline__ void load_chunk(uint32_t st, int k0,
                                           const u16* Ahb, const u16* Alb,
                                           const u16* Bhb, const u16* Blb,
                                           int lda, int ldb, int tid) {
    #pragma unroll
    for (int it = 0; it < 2; it++) {
        int id = tid + (it << 8);
        int row = id >> 2, kc = id & 3;
        uint32_t off = row * 80 + kc * 16;
        size_t ga = (size_t)row * lda + k0 + kc * 8;
        size_t gb2 = (size_t)row * ldb + k0 + kc * 8;
        cpa16(st + off,         Ahb + ga);
        cpa16(st + 10240 + off, Alb + ga);
        cpa16(st + 20480 + off, Bhb + gb2);
        cpa16(st + 30720 + off, Blb + gb2);
    }
}

// ---------------- split-bf16 mma.sync GEMM ----------------
// D[m,n] = sum_k A(m,k)*B(n,k); 128x128 tile; A/B pre-split bf16 hi/lo, k-major.
// EPI: 0 scores (exp(alpha*S) split store + row partial sums into outF),
//      1 AV (scale by rsum (outF) then split store),
//      2 qkv (bias; q/k transposed split, v split), 3 proj (bias + resid, fp32)
template <int EPI>
__global__ void __launch_bounds__(256, 2)
gemm_mma(const u16* __restrict__ Ah, const u16* __restrict__ Al, long long sA, int lda,
         const u16* __restrict__ Bh, const u16* __restrict__ Bl, long long sB, int ldb,
         int K, int ldc, long long sOut, float alpha,
         const float* __restrict__ bias, const float* __restrict__ resid,
         float* __restrict__ outF,
         u16* __restrict__ o1h, u16* __restrict__ o1l,
         u16* __restrict__ o2h, u16* __restrict__ o2l,
         u16* __restrict__ o3h, u16* __restrict__ o3l) {
    extern __shared__ __align__(16) char smem[];
    const int tid = threadIdx.x;
    const int wid = tid >> 5, lane = tid & 31;
    const int wm = wid >> 1, wn = wid & 1;
    const int m0 = blockIdx.y * 128, n0 = blockIdx.x * 128, bz = blockIdx.z;

    const u16* Ahb = Ah + sA * bz + (size_t)m0 * lda;
    const u16* Alb = Al + sA * bz + (size_t)m0 * lda;
    const u16* Bhb = Bh + sB * bz + (size_t)n0 * ldb;
    const u16* Blb = Bl + sB * bz + (size_t)n0 * ldb;

    const uint32_t sb = smem_u32(smem);

    float acc[2][8][4] = {};

    // ldmatrix lane address components
    const int ar  = lane & 15;
    const int akb = (lane >> 4) << 4;                       // 0/16 bytes
    const int br  = (lane & 7) + ((lane >> 4) << 3);
    const int bkb = ((lane >> 3) & 1) << 4;
    uint32_t aRow[2], bRow[4];
    #pragma unroll
    for (int mt = 0; mt < 2; mt++) aRow[mt] = (uint32_t)((wm * 32 + mt * 16 + ar) * 80 + akb);
    #pragma unroll
    for (int nt2 = 0; nt2 < 4; nt2++) bRow[nt2] = (uint32_t)((wn * 64 + nt2 * 16 + br) * 80 + bkb);

    load_chunk(sb, 0, Ahb, Alb, Bhb, Blb, lda, ldb, tid);
    asm volatile("cp.async.commit_group;" ::: "memory");

    const int NC = K >> 5;
    for (int c = 0; c < NC; c++) {
        asm volatile("cp.async.wait_group 0;" ::: "memory");
        __syncthreads();
        if (c + 1 < NC) {
            load_chunk(sb + ((c + 1) & 1) * 40960, (c + 1) << 5, Ahb, Alb, Bhb, Blb, lda, ldb, tid);
            asm volatile("cp.async.commit_group;" ::: "memory");
        }
        uint32_t st = sb + (c & 1) * 40960;
        #pragma unroll
        for (int ks = 0; ks < 2; ks++) {
            uint32_t a_h[2][4], a_l[2][4];
            #pragma unroll
            for (int mt = 0; mt < 2; mt++) {
                ldmx4(a_h[mt], st + aRow[mt] + ks * 32);
                ldmx4(a_l[mt], st + 10240 + aRow[mt] + ks * 32);
            }
            #pragma unroll
            for (int nt2 = 0; nt2 < 4; nt2++) {
                uint32_t b_h[4], b_l[4];
                ldmx4(b_h, st + 20480 + bRow[nt2] + ks * 32);
                ldmx4(b_l, st + 30720 + bRow[nt2] + ks * 32);
                #pragma unroll
                for (int mt = 0; mt < 2; mt++) {
                    mma16816(acc[mt][nt2 * 2],     a_h[mt], b_h);
                    mma16816(acc[mt][nt2 * 2 + 1], a_h[mt], b_h + 2);
                }
                #pragma unroll
                for (int mt = 0; mt < 2; mt++) {
                    mma16816(acc[mt][nt2 * 2],     a_h[mt], b_l);
                    mma16816(acc[mt][nt2 * 2 + 1], a_h[mt], b_l + 2);
                }
                #pragma unroll
                for (int mt = 0; mt < 2; mt++) {
                    mma16816(acc[mt][nt2 * 2],     a_l[mt], b_h);
                    mma16816(acc[mt][nt2 * 2 + 1], a_l[mt], b_h + 2);
                }
            }
        }
    }

    const int rB = lane >> 2;
    const int cB = (lane & 3) * 2;

    if (EPI == 0) {
        // exp(alpha*S) -> split store + deterministic row partial sums
        u16* Oh = o1h + sOut * bz;
        u16* Ol = o1l + sOut * bz;
        float* part = outF + (size_t)bz * N_PIX * 64;
        #pragma unroll
        for (int mt = 0; mt < 2; mt++)
            #pragma unroll
            for (int h = 0; h < 2; h++) {
                int rowG = m0 + wm * 32 + mt * 16 + rB + h * 8;
                float rs = 0.f;
                #pragma unroll
                for (int nt = 0; nt < 8; nt++) {
                    int colG = n0 + wn * 64 + nt * 8 + cB;
                    float e0 = __expf(acc[mt][nt][h * 2]     * alpha);
                    float e1 = __expf(acc[mt][nt][h * 2 + 1] * alpha);
                    rs += e0 + e1;
                    uint32_t hv, lv;
                    split2(e0, e1, hv, lv);
                    size_t di = (size_t)rowG * ldc + colG;
                    *(uint32_t*)(Oh + di) = hv;
                    *(uint32_t*)(Ol + di) = lv;
                }
                rs += __shfl_xor_sync(0xFFFFFFFFu, rs, 1);
                rs += __shfl_xor_sync(0xFFFFFFFFu, rs, 2);
                if ((lane & 3) == 0)
                    part[(size_t)rowG * 64 + blockIdx.x * 2 + wn] = rs;
            }
    } else if (EPI == 1) {
        // AV: scale by reciprocal rowsum then split store
        u16* Oh = o1h + sOut * bz;
        u16* Ol = o1l + sOut * bz;
        const float* rsum = outF + (size_t)bz * N_PIX;
        #pragma unroll
        for (int mt = 0; mt < 2; mt++)
            #pragma unroll
            for (int h = 0; h < 2; h++) {
                int rowG = m0 + wm * 32 + mt * 16 + rB + h * 8;
                float inv = rsum[rowG];
                #pragma unroll
                for (int nt = 0; nt < 8; nt++) {
                    int colG = n0 + wn * 64 + nt * 8 + cB;
                    uint32_t hv, lv;
                    split2(acc[mt][nt][h * 2] * inv, acc[mt][nt][h * 2 + 1] * inv, hv, lv);
                    size_t di = (size_t)rowG * ldc + colG;
                    *(uint32_t*)(Oh + di) = hv;
                    *(uint32_t*)(Ol + di) = lv;
                }
            }
    } else if (EPI == 3) {
        float* Ob = outF + sOut * bz;
        const float* Rb = resid + sOut * bz;
        #pragma unroll
        for (int mt = 0; mt < 2; mt++)
            #pragma unroll
            for (int nt = 0; nt < 8; nt++)
                #pragma unroll
                for (int h = 0; h < 2; h++) {
                    int rowG = m0 + wm * 32 + mt * 16 + rB + h * 8;
                    int colG = n0 + wn * 64 + nt * 8 + cB;
                    float bv = bias[rowG];
                    size_t di = (size_t)rowG * ldc + colG;
                    float2 rv = *(const float2*)(Rb + di);
                    float2 v = make_float2(acc[mt][nt][h * 2] + bv + rv.x,
                                           acc[mt][nt][h * 2 + 1] + bv + rv.y);
                    *(float2*)(Ob + di) = v;
                }
    } else {  // EPI 2: qkv
        int sect = m0 >> 8;
        int msub = m0 & 255;
        if (sect == 2) {   // v: split store [c][4096] + bias
            u16* Vh = o3h + (size_t)1048576 * bz;
            u16* Vl = o3l + (size_t)1048576 * bz;
            #pragma unroll
            for (int mt = 0; mt < 2; mt++)
                #pragma unroll
                for (int nt = 0; nt < 8; nt++)
                    #pragma unroll
                    for (int h = 0; h < 2; h++) {
                        int rowL = wm * 32 + mt * 16 + rB + h * 8;
                        float bv = bias[m0 + rowL];
                        int colG = n0 + wn * 64 + nt * 8 + cB;
                        uint32_t hv, lv;
                        split2(acc[mt][nt][h * 2] + bv, acc[mt][nt][h * 2 + 1] + bv, hv, lv);
                        size_t di = (size_t)(msub + rowL) * N_PIX + colG;
                        *(uint32_t*)(Vh + di) = hv;
                        *(uint32_t*)(Vl + di) = lv;
                    }
        } else {           // q/k: transpose via SMEM bounce -> [n][256]
            u16* Dh = (sect ? o2h : o1h) + (size_t)1048576 * bz;
            u16* Dl = (sect ? o2l : o1l) + (size_t)1048576 * bz;
            float* tsm = (float*)smem;
            __syncthreads();
            #pragma unroll
            for (int mt = 0; mt < 2; mt++)
                #pragma unroll
                for (int h = 0; h < 2; h++) {
                    int rowL = wm * 32 + mt * 16 + rB + h * 8;
                    float bv = bias[m0 + rowL];
                    #pragma unroll
                    for (int nt = 0; nt < 8; nt++) {
                        int colL = wn * 64 + nt * 8 + cB;
                        tsm[rowL * 133 + colL]     = acc[mt][nt][h * 2] + bv;
                        tsm[rowL * 133 + colL + 1] = acc[mt][nt][h * 2 + 1] + bv;
                    }
                }
            __syncthreads();
            #pragma unroll
            for (int it = 0; it < 32; it++) {
                int lin = tid + (it << 8);
                int n  = lin >> 6;
                int op = (lin & 63) << 1;
                float f0 = tsm[op * 133 + n];
                float f1 = tsm[(op + 1) * 133 + n];
                uint32_t hv, lv;
                split2(f0, f1, hv, lv);
                size_t di = (size_t)(n0 + n) * C_CH + msub + op;
                *(uint32_t*)(Dh + di) = hv;
                *(uint32_t*)(Dl + di) = lv;
            }
        }
    }
}

// ---------------- launch ----------------
extern "C" void kernel_launch(void* const* d_in, const int* in_sizes, int n_in,
                              void* d_out, int out_size) {
    const float* x      = (const float*)d_in[0];
    const float* gn_w   = (const float*)d_in[1];
    const float* gn_b   = (const float*)d_in[2];
    const float* qkv_w  = (const float*)d_in[3];
    const float* qkv_b  = (const float*)d_in[4];
    const float* proj_w = (const float*)d_in[5];
    const float* proj_b = (const float*)d_in[6];
    float* out = (float*)d_out;

    u16 *wh, *wl, *ph, *pl, *xnh, *xnl, *qTh, *qTl, *kTh, *kTl, *vh, *vl, *ah, *al, *oh, *ol;
    float *part, *rsum;
    cudaGetSymbolAddress((void**)&wh, g_wh);   cudaGetSymbolAddress((void**)&wl, g_wl);
    cudaGetSymbolAddress((void**)&ph, g_ph);   cudaGetSymbolAddress((void**)&pl, g_pl);
    cudaGetSymbolAddress((void**)&xnh, g_xnh); cudaGetSymbolAddress((void**)&xnl, g_xnl);
    cudaGetSymbolAddress((void**)&qTh, g_qTh); cudaGetSymbolAddress((void**)&qTl, g_qTl);
    cudaGetSymbolAddress((void**)&kTh, g_kTh); cudaGetSymbolAddress((void**)&kTl, g_kTl);
    cudaGetSymbolAddress((void**)&vh, g_vh);   cudaGetSymbolAddress((void**)&vl, g_vl);
    cudaGetSymbolAddress((void**)&ah, g_ah);   cudaGetSymbolAddress((void**)&al, g_al);
    cudaGetSymbolAddress((void**)&oh, g_oh);   cudaGetSymbolAddress((void**)&ol, g_ol);
    cudaGetSymbolAddress((void**)&part, g_part);
    cudaGetSymbolAddress((void**)&rsum, g_rsum);

    cudaFuncSetAttribute(gemm_mma<0>, cudaFuncAttributeMaxDynamicSharedMemorySize, SMEMSZ);
    cudaFuncSetAttribute(gemm_mma<1>, cudaFuncAttributeMaxDynamicSharedMemorySize, SMEMSZ);
    cudaFuncSetAttribute(gemm_mma<2>, cudaFuncAttributeMaxDynamicSharedMemorySize, SMEMSZ);
    cudaFuncSetAttribute(gemm_mma<3>, cudaFuncAttributeMaxDynamicSharedMemorySize, SMEMSZ);

    const long long sNC  = (long long)N_PIX * C_CH;      // 1M
    const long long sATT = (long long)N_PIX * N_PIX;     // 16M

    // 0) split weights
    split_w<<<1024, 256>>>(qkv_w, proj_w, wh, wl, ph, pl);

    // 1) GroupNorm -> xn^T hi/lo
    gn_split<<<64, 256>>>(x, gn_w, gn_b, xnh, xnl);

    // 2) QKV: D[o,n] = sum_c W[o,c] xnT[n,c]; -> qT/kT (transposed split), v (split)
    gemm_mma<2><<<dim3(32, 6, B_SZ), 256, SMEMSZ>>>(
        wh, wl, 0, C_CH, xnh, xnl, sNC, C_CH, C_CH, 0, 0, 1.0f,
        qkv_b, nullptr, nullptr, qTh, qTl, kTh, kTl, vh, vl);

    // 3) scores+exp: P~[i,j] = exp((1/16) sum_c qT[i,c] kT[j,c]) -> split + partial sums
    gemm_mma<0><<<dim3(32, 32, B_SZ), 256, SMEMSZ>>>(
        qTh, qTl, sNC, C_CH, kTh, kTl, sNC, C_CH, C_CH, N_PIX, sATT, 0.0625f,
        nullptr, nullptr, part, ah, al, nullptr, nullptr, nullptr, nullptr);

    // 4) rowsum reduce -> reciprocal sums
    rowsum_reduce<<<(B_SZ * N_PIX) / 8, 256>>>(part, rsum);

    // 5) AV: O[i,c] = (sum_m P~[i,m] v[c,m]) / rowsum_i -> split store [i][c]
    gemm_mma<1><<<dim3(2, 32, B_SZ), 256, SMEMSZ>>>(
        ah, al, sATT, N_PIX, vh, vl, sNC, N_PIX, N_PIX, C_CH, sNC, 1.0f,
        nullptr, nullptr, rsum, oh, ol, nullptr, nullptr, nullptr, nullptr);

    // 6) proj: out[o,i] = sum_c P[o,c] O[i,c] + pb[o] + x
    gemm_mma<3><<<dim3(32, 2, B_SZ), 256, SMEMSZ>>>(
        ph, pl, 0, C_CH, oh, ol, sNC, C_CH, C_CH, N_PIX, sNC, 1.0f,
        proj_b, x, out, nullptr, nullptr, nullptr, nullptr, nullptr, nullptr);
}

// round 6
// speedup vs baseline: 4.0885x; 1.3537x over previous
#include <cuda_runtime.h>
#include <cuda_fp16.h>
#include <cstdint>

#define B_SZ  8
#define C_CH  256
#define N_PIX 4096

typedef unsigned short u16;

// ---------------- scratch (device globals) ----------------
__device__ u16 g_wh[768 * 256],  g_wl[768 * 256];
__device__ u16 g_ph[256 * 256],  g_pl[256 * 256];
__device__ u16 g_xnh[B_SZ * N_PIX * C_CH], g_xnl[B_SZ * N_PIX * C_CH];   // xn^T [b][n][c] split
__device__ u16 g_qT [B_SZ * N_PIX * C_CH];                               // q^T plain fp16
__device__ u16 g_kTh[B_SZ * N_PIX * C_CH], g_kTl[B_SZ * N_PIX * C_CH];   // k^T split
__device__ u16 g_vh [B_SZ * C_CH * N_PIX], g_vl [B_SZ * C_CH * N_PIX];   // v [b][c][m] split
__device__ u16 g_P  [(size_t)B_SZ * N_PIX * N_PIX];                      // P~ plain fp16 (256MB)
__device__ float g_part[(size_t)B_SZ * N_PIX * 64];                      // row partial sums
__device__ float g_rsum[B_SZ * N_PIX];                                   // reciprocal row sums
__device__ u16 g_oh[B_SZ * N_PIX * C_CH], g_ol[B_SZ * N_PIX * C_CH];     // O [b][i][c] split

// ---------------- helpers ----------------
__device__ __forceinline__ uint32_t smem_u32(const void* p) {
    uint32_t a;
    asm("{ .reg .u64 t; cvta.to.shared.u64 t, %1; cvt.u32.u64 %0, t; }" : "=r"(a) : "l"(p));
    return a;
}
__device__ __forceinline__ u16 hbits(float v) {
    return __half_as_ushort(__float2half_rn(v));
}
__device__ __forceinline__ float hval(u16 u) { return __half2float(__ushort_as_half(u)); }
__device__ __forceinline__ uint32_t pk(u16 a, u16 b) { return (uint32_t)a | ((uint32_t)b << 16); }
__device__ __forceinline__ void split2(float f0, float f1, uint32_t& h, uint32_t& l) {
    u16 h0 = hbits(f0), h1 = hbits(f1);
    u16 l0 = hbits(f0 - hval(h0)), l1 = hbits(f1 - hval(h1));
    h = pk(h0, h1); l = pk(l0, l1);
}
__device__ __forceinline__ void cpa16(uint32_t dst, const void* src) {
    asm volatile("cp.async.cg.shared.global [%0], [%1], 16;" :: "r"(dst), "l"(src));
}
__device__ __forceinline__ void ldmx4(uint32_t* r, uint32_t addr) {
    asm volatile("ldmatrix.sync.aligned.m8n8.x4.shared.b16 {%0,%1,%2,%3}, [%4];"
                 : "=r"(r[0]), "=r"(r[1]), "=r"(r[2]), "=r"(r[3]) : "r"(addr));
}
__device__ __forceinline__ void mma16816(float* c, const uint32_t* a, const uint32_t* b) {
    asm volatile("mma.sync.aligned.m16n8k16.row.col.f32.f16.f16.f32 "
                 "{%0,%1,%2,%3},{%4,%5,%6,%7},{%8,%9},{%0,%1,%2,%3};"
                 : "+f"(c[0]), "+f"(c[1]), "+f"(c[2]), "+f"(c[3])
                 : "r"(a[0]), "r"(a[1]), "r"(a[2]), "r"(a[3]), "r"(b[0]), "r"(b[1]));
}

#define SMEM3 81920   // 3-term: 2 stages * 4 pieces * 10240
#define SMEM2 61440   // 2-term: 2 stages * 3 pieces * 10240

// ---------------- prep: split weights (fp16) ----------------
__global__ void split_w(const float* __restrict__ qw, const float* __restrict__ pw,
                        u16* qh, u16* ql, u16* ph_, u16* pl_) {
    int i = blockIdx.x * 256 + threadIdx.x;
    if (i < 768 * 256) {
        float v = qw[i];
        u16 h = hbits(v);
        qh[i] = h; ql[i] = hbits(v - hval(h));
    } else {
        int j = i - 768 * 256;
        float v = pw[j];
        u16 h = hbits(v);
        ph_[j] = h; pl_[j] = hbits(v - hval(h));
    }
}

// ---------------- GroupNorm -> split transposed xn^T [b][n][c] ----------------
__global__ void __launch_bounds__(256) gn_split(const float* __restrict__ x,
                                                const float* __restrict__ gw,
                                                const float* __restrict__ gb,
                                                u16* __restrict__ xh,
                                                u16* __restrict__ xl) {
    int b = blockIdx.x >> 3, g = blockIdx.x & 7;
    const size_t base = ((size_t)b * C_CH + g * 32) * N_PIX;
    const float* xp = x + base;
    const int TOT = 32 * N_PIX;

    float s = 0.f, s2 = 0.f;
    for (int i = threadIdx.x; i < TOT; i += 256) {
        float v = xp[i]; s += v; s2 += v * v;
    }
    #pragma unroll
    for (int o = 16; o > 0; o >>= 1) {
        s  += __shfl_xor_sync(0xFFFFFFFFu, s,  o);
        s2 += __shfl_xor_sync(0xFFFFFFFFu, s2, o);
    }
    __shared__ float shs[8], shs2[8], s_mean, s_inv, sgw[32], sgb[32];
    int wid = threadIdx.x >> 5, lid = threadIdx.x & 31;
    if (lid == 0) { shs[wid] = s; shs2[wid] = s2; }
    __syncthreads();
    if (threadIdx.x == 0) {
        float ts = 0.f, ts2 = 0.f;
        #pragma unroll
        for (int i = 0; i < 8; i++) { ts += shs[i]; ts2 += shs2[i]; }
        float mean = ts / (float)TOT;
        float var  = ts2 / (float)TOT - mean * mean;
        s_mean = mean; s_inv = rsqrtf(var + 1e-5f);
    }
    if (threadIdx.x < 32) { sgw[threadIdx.x] = gw[g * 32 + threadIdx.x]; sgb[threadIdx.x] = gb[g * 32 + threadIdx.x]; }
    __syncthreads();
    float mean = s_mean, inv = s_inv;

    for (int rep = 0; rep < 16; rep++) {
        int n = threadIdx.x + (rep << 8);
        uint32_t hb[16], lb[16];
        #pragma unroll
        for (int c2 = 0; c2 < 16; c2++) {
            int c = c2 * 2;
            float v0 = (xp[(size_t)c * N_PIX + n]       - mean) * inv * sgw[c]     + sgb[c];
            float v1 = (xp[(size_t)(c + 1) * N_PIX + n] - mean) * inv * sgw[c + 1] + sgb[c + 1];
            split2(v0, v1, hb[c2], lb[c2]);
        }
        size_t di = ((size_t)b * N_PIX + n) * C_CH + g * 32;
        #pragma unroll
        for (int q = 0; q < 4; q++) {
            *(uint4*)(xh + di + q * 8) = make_uint4(hb[q*4], hb[q*4+1], hb[q*4+2], hb[q*4+3]);
            *(uint4*)(xl + di + q * 8) = make_uint4(lb[q*4], lb[q*4+1], lb[q*4+2], lb[q*4+3]);
        }
    }
}

// ---------------- rowsum reduce ----------------
__global__ void __launch_bounds__(256) rowsum_reduce(const float* __restrict__ part,
                                                     float* __restrict__ rsum) {
    int gw = (blockIdx.x * 256 + threadIdx.x) >> 5;
    int lane = threadIdx.x & 31;
    const float* p = part + (size_t)gw * 64;
    float s = p[lane] + p[lane + 32];
    #pragma unroll
    for (int o = 16; o > 0; o >>= 1) s += __shfl_xor_sync(0xFFFFFFFFu, s, o);
    if (lane == 0) rsum[gw] = 1.0f / s;
}

// ---------------- chunk loaders (128x32 fp16 pieces, 80B rows) ----------------
template <int TERMS>
__device__ __forceinline__ void load_chunk(uint32_t st, int k0,
                                           const u16* Ahb, const u16* Alb,
                                           const u16* Bhb, const u16* Blb,
                                           int lda, int ldb, int tid) {
    #pragma unroll
    for (int it = 0; it < 2; it++) {
        int id = tid + (it << 8);
        int row = id >> 2, kc = id & 3;
        uint32_t off = row * 80 + kc * 16;
        size_t ga = (size_t)row * lda + k0 + kc * 8;
        size_t gb2 = (size_t)row * ldb + k0 + kc * 8;
        if (TERMS == 3) {
            cpa16(st + off,         Ahb + ga);
            cpa16(st + 10240 + off, Alb + ga);
            cpa16(st + 20480 + off, Bhb + gb2);
            cpa16(st + 30720 + off, Blb + gb2);
        } else {
            cpa16(st + off,         Ahb + ga);
            cpa16(st + 10240 + off, Bhb + gb2);
            cpa16(st + 20480 + off, Blb + gb2);
        }
    }
}

// ---------------- split-fp16 mma.sync GEMM ----------------
// D[m,n] = sum_k A(m,k)*B(n,k); 128x128 tile; k-major.
// TERMS=3: A split (Ah+Al), B split -> 3 MMA/16k.  TERMS=2: A plain, B split -> 2 MMA/16k.
// EPI: 0 scores (exp(alpha*S) -> plain fp16 P + row partial sums into outF),
//      1 AV (scale by rsum (outF), split store),
//      2 qkv (bias; q plain transposed, k split transposed, v split), 3 proj (bias+resid fp32)
template <int TERMS, int EPI>
__global__ void __launch_bounds__(256, 2)
gemm_mma(const u16* __restrict__ Ah, const u16* __restrict__ Al, long long sA, int lda,
         const u16* __restrict__ Bh, const u16* __restrict__ Bl, long long sB, int ldb,
         int K, int ldc, long long sOut, float alpha,
         const float* __restrict__ bias, const float* __restrict__ resid,
         float* __restrict__ outF,
         u16* __restrict__ o1h, u16* __restrict__ o1l,
         u16* __restrict__ o2h, u16* __restrict__ o2l,
         u16* __restrict__ o3h, u16* __restrict__ o3l) {
    extern __shared__ __align__(16) char smem[];
    const int tid = threadIdx.x;
    const int wid = tid >> 5, lane = tid & 31;
    const int wm = wid >> 1, wn = wid & 1;
    const int m0 = blockIdx.y * 128, n0 = blockIdx.x * 128, bz = blockIdx.z;

    const int STAGE = (TERMS == 3) ? 40960 : 30720;
    const int BOFF  = (TERMS == 3) ? 20480 : 10240;

    const u16* Ahb = Ah + sA * bz + (size_t)m0 * lda;
    const u16* Alb = (TERMS == 3) ? (Al + sA * bz + (size_t)m0 * lda) : nullptr;
    const u16* Bhb = Bh + sB * bz + (size_t)n0 * ldb;
    const u16* Blb = Bl + sB * bz + (size_t)n0 * ldb;

    const uint32_t sb = smem_u32(smem);

    float acc[2][8][4] = {};

    const int ar  = lane & 15;
    const int akb = (lane >> 4) << 4;
    const int br  = (lane & 7) + ((lane >> 4) << 3);
    const int bkb = ((lane >> 3) & 1) << 4;
    uint32_t aRow[2], bRow[4];
    #pragma unroll
    for (int mt = 0; mt < 2; mt++) aRow[mt] = (uint32_t)((wm * 32 + mt * 16 + ar) * 80 + akb);
    #pragma unroll
    for (int nt2 = 0; nt2 < 4; nt2++) bRow[nt2] = (uint32_t)((wn * 64 + nt2 * 16 + br) * 80 + bkb);

    load_chunk<TERMS>(sb, 0, Ahb, Alb, Bhb, Blb, lda, ldb, tid);
    asm volatile("cp.async.commit_group;" ::: "memory");

    const int NC = K >> 5;
    for (int c = 0; c < NC; c++) {
        if (c + 1 < NC)
            load_chunk<TERMS>(sb + ((c + 1) & 1) * STAGE, (c + 1) << 5, Ahb, Alb, Bhb, Blb, lda, ldb, tid);
        asm volatile("cp.async.commit_group;" ::: "memory");
        asm volatile("cp.async.wait_group 1;" ::: "memory");
        __syncthreads();
        uint32_t st = sb + (c & 1) * STAGE;
        #pragma unroll
        for (int ks = 0; ks < 2; ks++) {
            uint32_t a_h[2][4], a_l[2][4];
            #pragma unroll
            for (int mt = 0; mt < 2; mt++) {
                ldmx4(a_h[mt], st + aRow[mt] + ks * 32);
                if (TERMS == 3) ldmx4(a_l[mt], st + 10240 + aRow[mt] + ks * 32);
            }
            #pragma unroll
            for (int nt2 = 0; nt2 < 4; nt2++) {
                uint32_t b_h[4], b_l[4];
                ldmx4(b_h, st + BOFF + bRow[nt2] + ks * 32);
                ldmx4(b_l, st + BOFF + 10240 + bRow[nt2] + ks * 32);
                #pragma unroll
                for (int mt = 0; mt < 2; mt++) {
                    mma16816(acc[mt][nt2 * 2],     a_h[mt], b_h);
                    mma16816(acc[mt][nt2 * 2 + 1], a_h[mt], b_h + 2);
                }
                #pragma unroll
                for (int mt = 0; mt < 2; mt++) {
                    mma16816(acc[mt][nt2 * 2],     a_h[mt], b_l);
                    mma16816(acc[mt][nt2 * 2 + 1], a_h[mt], b_l + 2);
                }
                if (TERMS == 3) {
                    #pragma unroll
                    for (int mt = 0; mt < 2; mt++) {
                        mma16816(acc[mt][nt2 * 2],     a_l[mt], b_h);
                        mma16816(acc[mt][nt2 * 2 + 1], a_l[mt], b_h + 2);
                    }
                }
            }
        }
        __syncthreads();
    }

    const int rB = lane >> 2;
    const int cB = (lane & 3) * 2;

    if (EPI == 0) {
        // exp(alpha*S) -> plain fp16 P + deterministic row partial sums
        u16* P = o1h + sOut * bz;
        float* part = outF + (size_t)bz * N_PIX * 64;
        #pragma unroll
        for (int mt = 0; mt < 2; mt++)
            #pragma unroll
            for (int h = 0; h < 2; h++) {
                int rowG = m0 + wm * 32 + mt * 16 + rB + h * 8;
                float rs = 0.f;
                #pragma unroll
                for (int nt = 0; nt < 8; nt++) {
                    int colG = n0 + wn * 64 + nt * 8 + cB;
                    float e0 = __expf(acc[mt][nt][h * 2]     * alpha);
                    float e1 = __expf(acc[mt][nt][h * 2 + 1] * alpha);
                    rs += e0 + e1;
                    *(uint32_t*)(P + (size_t)rowG * ldc + colG) = pk(hbits(e0), hbits(e1));
                }
                rs += __shfl_xor_sync(0xFFFFFFFFu, rs, 1);
                rs += __shfl_xor_sync(0xFFFFFFFFu, rs, 2);
                if ((lane & 3) == 0)
                    part[(size_t)rowG * 64 + blockIdx.x * 2 + wn] = rs;
            }
    } else if (EPI == 1) {
        // AV: scale by reciprocal rowsum then split store
        u16* Oh = o1h + sOut * bz;
        u16* Ol = o1l + sOut * bz;
        const float* rsum = outF + (size_t)bz * N_PIX;
        #pragma unroll
        for (int mt = 0; mt < 2; mt++)
            #pragma unroll
            for (int h = 0; h < 2; h++) {
                int rowG = m0 + wm * 32 + mt * 16 + rB + h * 8;
                float inv = rsum[rowG];
                #pragma unroll
                for (int nt = 0; nt < 8; nt++) {
                    int colG = n0 + wn * 64 + nt * 8 + cB;
                    uint32_t hv, lv;
                    split2(acc[mt][nt][h * 2] * inv, acc[mt][nt][h * 2 + 1] * inv, hv, lv);
                    size_t di = (size_t)rowG * ldc + colG;
                    *(uint32_t*)(Oh + di) = hv;
                    *(uint32_t*)(Ol + di) = lv;
                }
            }
    } else if (EPI == 3) {
        float* Ob = outF + sOut * bz;
        const float* Rb = resid + sOut * bz;
        #pragma unroll
        for (int mt = 0; mt < 2; mt++)
            #pragma unroll
            for (int nt = 0; nt < 8; nt++)
                #pragma unroll
                for (int h = 0; h < 2; h++) {
                    int rowG = m0 + wm * 32 + mt * 16 + rB + h * 8;
                    int colG = n0 + wn * 64 + nt * 8 + cB;
                    float bv = bias[rowG];
                    size_t di = (size_t)rowG * ldc + colG;
                    float2 rv = *(const float2*)(Rb + di);
                    float2 v = make_float2(acc[mt][nt][h * 2] + bv + rv.x,
                                           acc[mt][nt][h * 2 + 1] + bv + rv.y);
                    *(float2*)(Ob + di) = v;
                }
    } else {  // EPI 2: qkv
        int sect = m0 >> 8;
        int msub = m0 & 255;
        if (sect == 2) {   // v: split store [c][4096] + bias
            u16* Vh = o3h + (size_t)1048576 * bz;
            u16* Vl = o3l + (size_t)1048576 * bz;
            #pragma unroll
            for (int mt = 0; mt < 2; mt++)
                #pragma unroll
                for (int nt = 0; nt < 8; nt++)
                    #pragma unroll
                    for (int h = 0; h < 2; h++) {
                        int rowL = wm * 32 + mt * 16 + rB + h * 8;
                        float bv = bias[m0 + rowL];
                        int colG = n0 + wn * 64 + nt * 8 + cB;
                        uint32_t hv, lv;
                        split2(acc[mt][nt][h * 2] + bv, acc[mt][nt][h * 2 + 1] + bv, hv, lv);
                        size_t di = (size_t)(msub + rowL) * N_PIX + colG;
                        *(uint32_t*)(Vh + di) = hv;
                        *(uint32_t*)(Vl + di) = lv;
                    }
        } else {           // q (plain) / k (split): transpose via SMEM bounce -> [n][256]
            u16* Dh = (sect ? o2h : o1h) + (size_t)1048576 * bz;
            u16* Dl = sect ? (o2l + (size_t)1048576 * bz) : nullptr;
            float* tsm = (float*)smem;
            __syncthreads();
            #pragma unroll
            for (int mt = 0; mt < 2; mt++)
                #pragma unroll
                for (int h = 0; h < 2; h++) {
                    int rowL = wm * 32 + mt * 16 + rB + h * 8;
                    float bv = bias[m0 + rowL];
                    #pragma unroll
                    for (int nt = 0; nt < 8; nt++) {
                        int colL = wn * 64 + nt * 8 + cB;
                        tsm[rowL * 133 + colL]     = acc[mt][nt][h * 2] + bv;
                        tsm[rowL * 133 + colL + 1] = acc[mt][nt][h * 2 + 1] + bv;
                    }
                }
            __syncthreads();
            #pragma unroll
            for (int it = 0; it < 32; it++) {
                int lin = tid + (it << 8);
                int n  = lin >> 6;
                int op = (lin & 63) << 1;
                float f0 = tsm[op * 133 + n];
                float f1 = tsm[(op + 1) * 133 + n];
                size_t di = (size_t)(n0 + n) * C_CH + msub + op;
                if (sect == 0) {
                    *(uint32_t*)(Dh + di) = pk(hbits(f0), hbits(f1));
                } else {
                    uint32_t hv, lv;
                    split2(f0, f1, hv, lv);
                    *(uint32_t*)(Dh + di) = hv;
                    *(uint32_t*)(Dl + di) = lv;
                }
            }
        }
    }
}

// ---------------- launch ----------------
extern "C" void kernel_launch(void* const* d_in, const int* in_sizes, int n_in,
                              void* d_out, int out_size) {
    const float* x      = (const float*)d_in[0];
    const float* gn_w   = (const float*)d_in[1];
    const float* gn_b   = (const float*)d_in[2];
    const float* qkv_w  = (const float*)d_in[3];
    const float* qkv_b  = (const float*)d_in[4];
    const float* proj_w = (const float*)d_in[5];
    const float* proj_b = (const float*)d_in[6];
    float* out = (float*)d_out;

    u16 *wh, *wl, *ph, *pl, *xnh, *xnl, *qT, *kTh, *kTl, *vh, *vl, *P, *oh, *ol;
    float *part, *rsum;
    cudaGetSymbolAddress((void**)&wh, g_wh);   cudaGetSymbolAddress((void**)&wl, g_wl);
    cudaGetSymbolAddress((void**)&ph, g_ph);   cudaGetSymbolAddress((void**)&pl, g_pl);
    cudaGetSymbolAddress((void**)&xnh, g_xnh); cudaGetSymbolAddress((void**)&xnl, g_xnl);
    cudaGetSymbolAddress((void**)&qT, g_qT);
    cudaGetSymbolAddress((void**)&kTh, g_kTh); cudaGetSymbolAddress((void**)&kTl, g_kTl);
    cudaGetSymbolAddress((void**)&vh, g_vh);   cudaGetSymbolAddress((void**)&vl, g_vl);
    cudaGetSymbolAddress((void**)&P, g_P);
    cudaGetSymbolAddress((void**)&oh, g_oh);   cudaGetSymbolAddress((void**)&ol, g_ol);
    cudaGetSymbolAddress((void**)&part, g_part);
    cudaGetSymbolAddress((void**)&rsum, g_rsum);

    cudaFuncSetAttribute((const void*)gemm_mma<3, 2>, cudaFuncAttributeMaxDynamicSharedMemorySize, SMEM3);
    cudaFuncSetAttribute((const void*)gemm_mma<2, 0>, cudaFuncAttributeMaxDynamicSharedMemorySize, SMEM2);
    cudaFuncSetAttribute((const void*)gemm_mma<2, 1>, cudaFuncAttributeMaxDynamicSharedMemorySize, SMEM2);
    cudaFuncSetAttribute((const void*)gemm_mma<3, 3>, cudaFuncAttributeMaxDynamicSharedMemorySize, SMEM3);

    const long long sNC  = (long long)N_PIX * C_CH;      // 1M
    const long long sATT = (long long)N_PIX * N_PIX;     // 16M

    // 0) split weights
    split_w<<<1024, 256>>>(qkv_w, proj_w, wh, wl, ph, pl);

    // 1) GroupNorm -> xn^T hi/lo
    gn_split<<<64, 256>>>(x, gn_w, gn_b, xnh, xnl);

    // 2) QKV (3-term): D[o,n] = sum_c W[o,c] xnT[n,c] -> q plain T, k split T, v split
    gemm_mma<3, 2><<<dim3(32, 6, B_SZ), 256, SMEM3>>>(
        wh, wl, 0, C_CH, xnh, xnl, sNC, C_CH, C_CH, 0, 0, 1.0f,
        qkv_b, nullptr, nullptr, qT, nullptr, kTh, kTl, vh, vl);

    // 3) scores+exp (2-term): P~[i,j] = exp((1/16) sum_c qT[i,c] kT[j,c]) + partial sums
    gemm_mma<2, 0><<<dim3(32, 32, B_SZ), 256, SMEM2>>>(
        qT, nullptr, sNC, C_CH, kTh, kTl, sNC, C_CH, C_CH, N_PIX, sATT, 0.0625f,
        nullptr, nullptr, part, P, nullptr, nullptr, nullptr, nullptr, nullptr);

    // 4) rowsum reduce -> reciprocal sums
    rowsum_reduce<<<(B_SZ * N_PIX) / 8, 256>>>(part, rsum);

    // 5) AV (2-term): O[i,c] = (sum_m P~[i,m] v[c,m]) / rowsum_i -> split store [i][c]
    gemm_mma<2, 1><<<dim3(2, 32, B_SZ), 256, SMEM2>>>(
        P, nullptr, sATT, N_PIX, vh, vl, sNC, N_PIX, N_PIX, C_CH, sNC, 1.0f,
        nullptr, nullptr, rsum, oh, ol, nullptr, nullptr, nullptr, nullptr);

    // 6) proj (3-term): out[o,i] = sum_c Pw[o,c] O[i,c] + pb[o] + x
    gemm_mma<3, 3><<<dim3(32, 2, B_SZ), 256, SMEM3>>>(
        ph, pl, 0, C_CH, oh, ol, sNC, C_CH, C_CH, N_PIX, sNC, 1.0f,
        proj_b, x, out, nullptr, nullptr, nullptr, nullptr, nullptr, nullptr);
}

// round 8
// speedup vs baseline: 6.3173x; 1.5451x over previous
#include <cuda_runtime.h>
#include <cuda_fp16.h>
#include <cstdint>

#define B_SZ  8
#define C_CH  256
#define N_PIX 4096

typedef unsigned short u16;

// ---------------- scratch (device globals) ----------------
__device__ u16 g_wh[768 * 256],  g_wl[768 * 256];                        // qkv W split
__device__ u16 g_ph[256 * 256],  g_pl[256 * 256];                        // proj W split
__device__ u16 g_xn[B_SZ * N_PIX * C_CH];                                // xn^T [b][n][c] plain
__device__ u16 g_qT[B_SZ * N_PIX * C_CH];                                // q^T plain
__device__ u16 g_kT[B_SZ * N_PIX * C_CH];                                // k^T plain
__device__ u16 g_v [B_SZ * C_CH * N_PIX];                                // v [b][c][m] plain
__device__ u16 g_P [(size_t)B_SZ * N_PIX * N_PIX];                       // P~ plain (256MB)
__device__ float g_part[(size_t)B_SZ * N_PIX * 64];                      // row partial sums
__device__ float g_rsum[B_SZ * N_PIX];                                   // reciprocal row sums
__device__ u16 g_O [B_SZ * N_PIX * C_CH];                                // O [b][i][c] plain

// ---------------- helpers ----------------
__device__ __forceinline__ uint32_t smem_u32(const void* p) {
    uint32_t a;
    asm("{ .reg .u64 t; cvta.to.shared.u64 t, %1; cvt.u32.u64 %0, t; }" : "=r"(a) : "l"(p));
    return a;
}
__device__ __forceinline__ u16 hbits(float v) {
    return __half_as_ushort(__float2half_rn(v));
}
__device__ __forceinline__ float hval(u16 u) { return __half2float(__ushort_as_half(u)); }
__device__ __forceinline__ uint32_t pk(u16 a, u16 b) { return (uint32_t)a | ((uint32_t)b << 16); }
__device__ __forceinline__ void cpa16(uint32_t dst, const void* src) {
    asm volatile("cp.async.cg.shared.global [%0], [%1], 16;" :: "r"(dst), "l"(src));
}
__device__ __forceinline__ void ldmx4(uint32_t* r, uint32_t addr) {
    asm volatile("ldmatrix.sync.aligned.m8n8.x4.shared.b16 {%0,%1,%2,%3}, [%4];"
                 : "=r"(r[0]), "=r"(r[1]), "=r"(r[2]), "=r"(r[3]) : "r"(addr));
}
__device__ __forceinline__ void mma16816(float* c, const uint32_t* a, const uint32_t* b) {
    asm volatile("mma.sync.aligned.m16n8k16.row.col.f32.f16.f16.f32 "
                 "{%0,%1,%2,%3},{%4,%5,%6,%7},{%8,%9},{%0,%1,%2,%3};"
                 : "+f"(c[0]), "+f"(c[1]), "+f"(c[2]), "+f"(c[3])
                 : "r"(a[0]), "r"(a[1]), "r"(a[2]), "r"(a[3]), "r"(b[0]), "r"(b[1]));
}

#define SMEM_A1  40960   // ASPLIT=0: 2 stages * 2 pieces * 10240
#define SMEM_A2  61440   // ASPLIT=1: 2 stages * 3 pieces * 10240
#define SMEM_QKV 69632   // ASPLIT=1 + 128x133 fp32 transpose bounce (68096B)

// ---------------- prep: split weights (fp16) ----------------
__global__ void split_w(const float* __restrict__ qw, const float* __restrict__ pw,
                        u16* qh, u16* ql, u16* ph_, u16* pl_) {
    int i = blockIdx.x * 256 + threadIdx.x;
    if (i < 768 * 256) {
        float v = qw[i];
        u16 h = hbits(v);
        qh[i] = h; ql[i] = hbits(v - hval(h));
    } else {
        int j = i - 768 * 256;
        float v = pw[j];
        u16 h = hbits(v);
        ph_[j] = h; pl_[j] = hbits(v - hval(h));
    }
}

// ---------------- GroupNorm -> plain fp16 transposed xn^T [b][n][c] ----------------
__global__ void __launch_bounds__(256) gn_plain(const float* __restrict__ x,
                                                const float* __restrict__ gw,
                                                const float* __restrict__ gb,
                                                u16* __restrict__ xn) {
    int b = blockIdx.x >> 3, g = blockIdx.x & 7;
    const size_t base = ((size_t)b * C_CH + g * 32) * N_PIX;
    const float* xp = x + base;
    const int TOT = 32 * N_PIX;

    float s = 0.f, s2 = 0.f;
    for (int i = threadIdx.x; i < TOT; i += 256) {
        float v = xp[i]; s += v; s2 += v * v;
    }
    #pragma unroll
    for (int o = 16; o > 0; o >>= 1) {
        s  += __shfl_xor_sync(0xFFFFFFFFu, s,  o);
        s2 += __shfl_xor_sync(0xFFFFFFFFu, s2, o);
    }
    __shared__ float shs[8], shs2[8], s_mean, s_inv, sgw[32], sgb[32];
    int wid = threadIdx.x >> 5, lid = threadIdx.x & 31;
    if (lid == 0) { shs[wid] = s; shs2[wid] = s2; }
    __syncthreads();
    if (threadIdx.x == 0) {
        float ts = 0.f, ts2 = 0.f;
        #pragma unroll
        for (int i = 0; i < 8; i++) { ts += shs[i]; ts2 += shs2[i]; }
        float mean = ts / (float)TOT;
        float var  = ts2 / (float)TOT - mean * mean;
        s_mean = mean; s_inv = rsqrtf(var + 1e-5f);
    }
    if (threadIdx.x < 32) { sgw[threadIdx.x] = gw[g * 32 + threadIdx.x]; sgb[threadIdx.x] = gb[g * 32 + threadIdx.x]; }
    __syncthreads();
    float mean = s_mean, inv = s_inv;

    for (int rep = 0; rep < 16; rep++) {
        int n = threadIdx.x + (rep << 8);
        uint32_t hb[16];
        #pragma unroll
        for (int c2 = 0; c2 < 16; c2++) {
            int c = c2 * 2;
            float v0 = (xp[(size_t)c * N_PIX + n]       - mean) * inv * sgw[c]     + sgb[c];
            float v1 = (xp[(size_t)(c + 1) * N_PIX + n] - mean) * inv * sgw[c + 1] + sgb[c + 1];
            hb[c2] = pk(hbits(v0), hbits(v1));
        }
        size_t di = ((size_t)b * N_PIX + n) * C_CH + g * 32;
        #pragma unroll
        for (int q = 0; q < 4; q++)
            *(uint4*)(xn + di + q * 8) = make_uint4(hb[q*4], hb[q*4+1], hb[q*4+2], hb[q*4+3]);
    }
}

// ---------------- rowsum reduce ----------------
__global__ void __launch_bounds__(256) rowsum_reduce(const float* __restrict__ part,
                                                     float* __restrict__ rsum) {
    int gw = (blockIdx.x * 256 + threadIdx.x) >> 5;
    int lane = threadIdx.x & 31;
    const float* p = part + (size_t)gw * 64;
    float s = p[lane] + p[lane + 32];
    #pragma unroll
    for (int o = 16; o > 0; o >>= 1) s += __shfl_xor_sync(0xFFFFFFFFu, s, o);
    if (lane == 0) rsum[gw] = 1.0f / s;
}

// ---------------- chunk loaders (128x32 fp16 pieces, 80B rows) ----------------
template <int ASPLIT>
__device__ __forceinline__ void load_chunk(uint32_t st, int k0,
                                           const u16* Ahb, const u16* Alb,
                                           const u16* Bb,
                                           int lda, int ldb, int tid) {
    const uint32_t BOFF = (1 + ASPLIT) * 10240;
    #pragma unroll
    for (int it = 0; it < 2; it++) {
        int id = tid + (it << 8);
        int row = id >> 2, kc = id & 3;
        uint32_t off = row * 80 + kc * 16;
        size_t ga = (size_t)row * lda + k0 + kc * 8;
        size_t gb2 = (size_t)row * ldb + k0 + kc * 8;
        cpa16(st + off, Ahb + ga);
        if (ASPLIT) cpa16(st + 10240 + off, Alb + ga);
        cpa16(st + BOFF + off, Bb + gb2);
    }
}

// ---------------- fp16 mma.sync GEMM ----------------
// D[m,n] = sum_k A(m,k)*B(n,k); 128x128 tile; k-major; B always plain fp16.
// ASPLIT=1: A = Ah+Al (2 MMA/16k);  ASPLIT=0: A plain (1 MMA/16k).
// EPI: 0 scores (exp(alpha*S) -> plain P + partial sums), 1 AV (scale by rsum, plain store),
//      2 qkv (bias; q/k transposed plain, v plain), 3 proj (bias + resid, fp32)
template <int ASPLIT, int EPI>
__global__ void __launch_bounds__(256, 2)
gemm_mma(const u16* __restrict__ Ah, const u16* __restrict__ Al, long long sA, int lda,
         const u16* __restrict__ Bb, long long sB, int ldb,
         int K, int ldc, long long sOut, float alpha,
         const float* __restrict__ bias, const float* __restrict__ resid,
         float* __restrict__ outF,
         u16* __restrict__ o1, u16* __restrict__ o2, u16* __restrict__ o3) {
    extern __shared__ __align__(16) char smem[];
    const int tid = threadIdx.x;
    const int wid = tid >> 5, lane = tid & 31;
    const int wm = wid >> 1, wn = wid & 1;
    const int m0 = blockIdx.y * 128, n0 = blockIdx.x * 128, bz = blockIdx.z;

    const int STAGE = (2 + ASPLIT) * 10240;
    const int BOFF  = (1 + ASPLIT) * 10240;

    const u16* Ahb = Ah + sA * bz + (size_t)m0 * lda;
    const u16* Alb = ASPLIT ? (Al + sA * bz + (size_t)m0 * lda) : nullptr;
    const u16* Bpb = Bb + sB * bz + (size_t)n0 * ldb;

    const uint32_t sb = smem_u32(smem);

    float acc[2][8][4] = {};

    const int ar  = lane & 15;
    const int akb = (lane >> 4) << 4;
    const int br  = (lane & 7) + ((lane >> 4) << 3);
    const int bkb = ((lane >> 3) & 1) << 4;
    uint32_t aRow[2], bRow[4];
    #pragma unroll
    for (int mt = 0; mt < 2; mt++) aRow[mt] = (uint32_t)((wm * 32 + mt * 16 + ar) * 80 + akb);
    #pragma unroll
    for (int nt2 = 0; nt2 < 4; nt2++) bRow[nt2] = (uint32_t)((wn * 64 + nt2 * 16 + br) * 80 + bkb);

    load_chunk<ASPLIT>(sb, 0, Ahb, Alb, Bpb, lda, ldb, tid);
    asm volatile("cp.async.commit_group;" ::: "memory");

    const int NC = K >> 5;
    for (int c = 0; c < NC; c++) {
        if (c + 1 < NC)
            load_chunk<ASPLIT>(sb + ((c + 1) & 1) * STAGE, (c + 1) << 5, Ahb, Alb, Bpb, lda, ldb, tid);
        asm volatile("cp.async.commit_group;" ::: "memory");
        asm volatile("cp.async.wait_group 1;" ::: "memory");
        __syncthreads();
        uint32_t st = sb + (c & 1) * STAGE;
        #pragma unroll
        for (int ks = 0; ks < 2; ks++) {
            uint32_t a_h[2][4], a_l[2][4];
            #pragma unroll
            for (int mt = 0; mt < 2; mt++) {
                ldmx4(a_h[mt], st + aRow[mt] + ks * 32);
                if (ASPLIT) ldmx4(a_l[mt], st + 10240 + aRow[mt] + ks * 32);
            }
            #pragma unroll
            for (int nt2 = 0; nt2 < 4; nt2++) {
                uint32_t b_f[4];
                ldmx4(b_f, st + BOFF + bRow[nt2] + ks * 32);
                #pragma unroll
                for (int mt = 0; mt < 2; mt++) {
                    mma16816(acc[mt][nt2 * 2],     a_h[mt], b_f);
                    mma16816(acc[mt][nt2 * 2 + 1], a_h[mt], b_f + 2);
                }
                if (ASPLIT) {
                    #pragma unroll
                    for (int mt = 0; mt < 2; mt++) {
                        mma16816(acc[mt][nt2 * 2],     a_l[mt], b_f);
                        mma16816(acc[mt][nt2 * 2 + 1], a_l[mt], b_f + 2);
                    }
                }
            }
        }
        __syncthreads();
    }

    const int rB = lane >> 2;
    const int cB = (lane & 3) * 2;

    if (EPI == 0) {
        // exp(alpha*S) -> plain fp16 P + deterministic row partial sums
        u16* P = o1 + sOut * bz;
        float* part = outF + (size_t)bz * N_PIX * 64;
        #pragma unroll
        for (int mt = 0; mt < 2; mt++)
            #pragma unroll
            for (int h = 0; h < 2; h++) {
                int rowG = m0 + wm * 32 + mt * 16 + rB + h * 8;
                float rs = 0.f;
                #pragma unroll
                for (int nt = 0; nt < 8; nt++) {
                    int colG = n0 + wn * 64 + nt * 8 + cB;
                    float e0 = __expf(acc[mt][nt][h * 2]     * alpha);
                    float e1 = __expf(acc[mt][nt][h * 2 + 1] * alpha);
                    rs += e0 + e1;
                    *(uint32_t*)(P + (size_t)rowG * ldc + colG) = pk(hbits(e0), hbits(e1));
                }
                rs += __shfl_xor_sync(0xFFFFFFFFu, rs, 1);
                rs += __shfl_xor_sync(0xFFFFFFFFu, rs, 2);
                if ((lane & 3) == 0)
                    part[(size_t)rowG * 64 + blockIdx.x * 2 + wn] = rs;
            }
    } else if (EPI == 1) {
        // AV: scale by reciprocal rowsum then plain store
        u16* O = o1 + sOut * bz;
        const float* rsum = outF + (size_t)bz * N_PIX;
        #pragma unroll
        for (int mt = 0; mt < 2; mt++)
            #pragma unroll
            for (int h = 0; h < 2; h++) {
                int rowG = m0 + wm * 32 + mt * 16 + rB + h * 8;
                float inv = rsum[rowG];
                #pragma unroll
                for (int nt = 0; nt < 8; nt++) {
                    int colG = n0 + wn * 64 + nt * 8 + cB;
                    *(uint32_t*)(O + (size_t)rowG * ldc + colG) =
                        pk(hbits(acc[mt][nt][h * 2] * inv), hbits(acc[mt][nt][h * 2 + 1] * inv));
                }
            }
    } else if (EPI == 3) {
        float* Ob = outF + sOut * bz;
        const float* Rb = resid + sOut * bz;
        #pragma unroll
        for (int mt = 0; mt < 2; mt++)
            #pragma unroll
            for (int nt = 0; nt < 8; nt++)
                #pragma unroll
                for (int h = 0; h < 2; h++) {
                    int rowG = m0 + wm * 32 + mt * 16 + rB + h * 8;
                    int colG = n0 + wn * 64 + nt * 8 + cB;
                    float bv = bias[rowG];
                    size_t di = (size_t)rowG * ldc + colG;
                    float2 rv = *(const float2*)(Rb + di);
                    float2 v = make_float2(acc[mt][nt][h * 2] + bv + rv.x,
                                           acc[mt][nt][h * 2 + 1] + bv + rv.y);
                    *(float2*)(Ob + di) = v;
                }
    } else {  // EPI 2: qkv
        int sect = m0 >> 8;
        int msub = m0 & 255;
        if (sect == 2) {   // v: plain store [c][4096] + bias
            u16* V = o3 + (size_t)1048576 * bz;
            #pragma unroll
            for (int mt = 0; mt < 2; mt++)
                #pragma unroll
                for (int nt = 0; nt < 8; nt++)
                    #pragma unroll
                    for (int h = 0; h < 2; h++) {
                        int rowL = wm * 32 + mt * 16 + rB + h * 8;
                        float bv = bias[m0 + rowL];
                        int colG = n0 + wn * 64 + nt * 8 + cB;
                        *(uint32_t*)(V + (size_t)(msub + rowL) * N_PIX + colG) =
                            pk(hbits(acc[mt][nt][h * 2] + bv), hbits(acc[mt][nt][h * 2 + 1] + bv));
                    }
        } else {           // q/k: transpose via SMEM bounce -> plain [n][256]
            u16* D = (sect ? o2 : o1) + (size_t)1048576 * bz;
            float* tsm = (float*)smem;
            __syncthreads();
            #pragma unroll
            for (int mt = 0; mt < 2; mt++)
                #pragma unroll
                for (int h = 0; h < 2; h++) {
                    int rowL = wm * 32 + mt * 16 + rB + h * 8;
                    float bv = bias[m0 + rowL];
                    #pragma unroll
                    for (int nt = 0; nt < 8; nt++) {
                        int colL = wn * 64 + nt * 8 + cB;
                        tsm[rowL * 133 + colL]     = acc[mt][nt][h * 2] + bv;
                        tsm[rowL * 133 + colL + 1] = acc[mt][nt][h * 2 + 1] + bv;
                    }
                }
            __syncthreads();
            #pragma unroll
            for (int it = 0; it < 32; it++) {
                int lin = tid + (it << 8);
                int n  = lin >> 6;
                int op = (lin & 63) << 1;
                float f0 = tsm[op * 133 + n];
                float f1 = tsm[(op + 1) * 133 + n];
                *(uint32_t*)(D + (size_t)(n0 + n) * C_CH + msub + op) = pk(hbits(f0), hbits(f1));
            }
        }
    }
}

// ---------------- launch ----------------
extern "C" void kernel_launch(void* const* d_in, const int* in_sizes, int n_in,
                              void* d_out, int out_size) {
    const float* x      = (const float*)d_in[0];
    const float* gn_w   = (const float*)d_in[1];
    const float* gn_b   = (const float*)d_in[2];
    const float* qkv_w  = (const float*)d_in[3];
    const float* qkv_b  = (const float*)d_in[4];
    const float* proj_w = (const float*)d_in[5];
    const float* proj_b = (const float*)d_in[6];
    float* out = (float*)d_out;

    u16 *wh, *wl, *ph, *pl, *xn, *qT, *kT, *v, *P, *O;
    float *part, *rsum;
    cudaGetSymbolAddress((void**)&wh, g_wh);   cudaGetSymbolAddress((void**)&wl, g_wl);
    cudaGetSymbolAddress((void**)&ph, g_ph);   cudaGetSymbolAddress((void**)&pl, g_pl);
    cudaGetSymbolAddress((void**)&xn, g_xn);
    cudaGetSymbolAddress((void**)&qT, g_qT);   cudaGetSymbolAddress((void**)&kT, g_kT);
    cudaGetSymbolAddress((void**)&v, g_v);     cudaGetSymbolAddress((void**)&P, g_P);
    cudaGetSymbolAddress((void**)&O, g_O);
    cudaGetSymbolAddress((void**)&part, g_part);
    cudaGetSymbolAddress((void**)&rsum, g_rsum);

    cudaFuncSetAttribute((const void*)gemm_mma<1, 2>, cudaFuncAttributeMaxDynamicSharedMemorySize, SMEM_QKV);
    cudaFuncSetAttribute((const void*)gemm_mma<0, 0>, cudaFuncAttributeMaxDynamicSharedMemorySize, SMEM_A1);
    cudaFuncSetAttribute((const void*)gemm_mma<0, 1>, cudaFuncAttributeMaxDynamicSharedMemorySize, SMEM_A1);
    cudaFuncSetAttribute((const void*)gemm_mma<1, 3>, cudaFuncAttributeMaxDynamicSharedMemorySize, SMEM_A2);

    const long long sNC  = (long long)N_PIX * C_CH;      // 1M
    const long long sATT = (long long)N_PIX * N_PIX;     // 16M

    // 0) split weights
    split_w<<<1024, 256>>>(qkv_w, proj_w, wh, wl, ph, pl);

    // 1) GroupNorm -> xn^T plain fp16
    gn_plain<<<64, 256>>>(x, gn_w, gn_b, xn);

    // 2) QKV (A=W split, B=xn plain): -> q/k plain T, v plain
    gemm_mma<1, 2><<<dim3(32, 6, B_SZ), 256, SMEM_QKV>>>(
        wh, wl, 0, C_CH, xn, sNC, C_CH, C_CH, 0, 0, 1.0f,
        qkv_b, nullptr, nullptr, qT, kT, v);

    // 3) scores+exp (all plain): P~[i,j] = exp((1/16) sum_c qT[i,c] kT[j,c]) + partial sums
    gemm_mma<0, 0><<<dim3(32, 32, B_SZ), 256, SMEM_A1>>>(
        qT, nullptr, sNC, C_CH, kT, sNC, C_CH, C_CH, N_PIX, sATT, 0.0625f,
        nullptr, nullptr, part, P, nullptr, nullptr);

    // 4) rowsum reduce -> reciprocal sums
    rowsum_reduce<<<(B_SZ * N_PIX) / 8, 256>>>(part, rsum);

    // 5) AV (all plain): O[i,c] = (sum_m P~[i,m] v[c,m]) / rowsum_i -> plain store [i][c]
    gemm_mma<0, 1><<<dim3(2, 32, B_SZ), 256, SMEM_A1>>>(
        P, nullptr, sATT, N_PIX, v, sNC, N_PIX, N_PIX, C_CH, sNC, 1.0f,
        nullptr, nullptr, rsum, O, nullptr, nullptr);

    // 6) proj (A=P split, B=O plain): out[o,i] = sum_c Pw[o,c] O[i,c] + pb[o] + x
    gemm_mma<1, 3><<<dim3(32, 2, B_SZ), 256, SMEM_A2>>>(
        ph, pl, 0, C_CH, O, sNC, C_CH, C_CH, N_PIX, sNC, 1.0f,
        proj_b, x, out, nullptr, nullptr, nullptr);
}

// round 9
// speedup vs baseline: 7.1108x; 1.1256x over previous
#include <cuda_runtime.h>
#include <cuda_fp16.h>
#include <cstdint>

#define B_SZ  8
#define C_CH  256
#define N_PIX 4096

typedef unsigned short u16;

// ---------------- scratch (device globals) ----------------
__device__ u16 g_wh[768 * 256],  g_wl[768 * 256];                        // qkv W split
__device__ u16 g_ph[256 * 256],  g_pl[256 * 256];                        // proj W split
__device__ u16 g_xn[B_SZ * N_PIX * C_CH];                                // xn^T [b][n][c] plain
__device__ u16 g_qT[B_SZ * N_PIX * C_CH];                                // q^T plain
__device__ u16 g_kT[B_SZ * N_PIX * C_CH];                                // k^T plain
__device__ u16 g_v [B_SZ * C_CH * N_PIX];                                // v [b][c][m] plain
__device__ u16 g_P [(size_t)B_SZ * N_PIX * N_PIX];                       // P~ plain (256MB)
__device__ float g_part[(size_t)B_SZ * N_PIX * 64];                      // row partial sums
__device__ float g_rsum[B_SZ * N_PIX];                                   // reciprocal row sums
__device__ u16 g_O [B_SZ * N_PIX * C_CH];                                // O [b][i][c] plain

// ---------------- helpers ----------------
__device__ __forceinline__ uint32_t smem_u32(const void* p) {
    uint32_t a;
    asm("{ .reg .u64 t; cvta.to.shared.u64 t, %1; cvt.u32.u64 %0, t; }" : "=r"(a) : "l"(p));
    return a;
}
__device__ __forceinline__ u16 hbits(float v) {
    return __half_as_ushort(__float2half_rn(v));
}
__device__ __forceinline__ float hval(u16 u) { return __half2float(__ushort_as_half(u)); }
__device__ __forceinline__ uint32_t pk(u16 a, u16 b) { return (uint32_t)a | ((uint32_t)b << 16); }
__device__ __forceinline__ void cpa16(uint32_t dst, const void* src) {
    asm volatile("cp.async.cg.shared.global [%0], [%1], 16;" :: "r"(dst), "l"(src));
}
__device__ __forceinline__ void ldmx4(uint32_t* r, uint32_t addr) {
    asm volatile("ldmatrix.sync.aligned.m8n8.x4.shared.b16 {%0,%1,%2,%3}, [%4];"
                 : "=r"(r[0]), "=r"(r[1]), "=r"(r[2]), "=r"(r[3]) : "r"(addr));
}
__device__ __forceinline__ void mma16816(float* c, const uint32_t* a, const uint32_t* b) {
    asm volatile("mma.sync.aligned.m16n8k16.row.col.f32.f16.f16.f32 "
                 "{%0,%1,%2,%3},{%4,%5,%6,%7},{%8,%9},{%0,%1,%2,%3};"
                 : "+f"(c[0]), "+f"(c[1]), "+f"(c[2]), "+f"(c[3])
                 : "r"(a[0]), "r"(a[1]), "r"(a[2]), "r"(a[3]), "r"(b[0]), "r"(b[1]));
}

// K-chunk = 64: piece = 128 rows x 128B (swizzled), 16KB
#define PIECE 16384
#define SMEM_A1 98304   // ASPLIT=0: 3 stages * 2 pieces
#define SMEM_A2 98304   // ASPLIT=1: 2 stages * 3 pieces (covers 68096B transpose bounce)

// ---------------- prep: split weights (fp16) ----------------
__global__ void split_w(const float* __restrict__ qw, const float* __restrict__ pw,
                        u16* qh, u16* ql, u16* ph_, u16* pl_) {
    int i = blockIdx.x * 256 + threadIdx.x;
    if (i < 768 * 256) {
        float v = qw[i];
        u16 h = hbits(v);
        qh[i] = h; ql[i] = hbits(v - hval(h));
    } else {
        int j = i - 768 * 256;
        float v = pw[j];
        u16 h = hbits(v);
        ph_[j] = h; pl_[j] = hbits(v - hval(h));
    }
}

// ---------------- GroupNorm -> plain fp16 transposed xn^T [b][n][c] ----------------
__global__ void __launch_bounds__(256) gn_plain(const float* __restrict__ x,
                                                const float* __restrict__ gw,
                                                const float* __restrict__ gb,
                                                u16* __restrict__ xn) {
    int b = blockIdx.x >> 3, g = blockIdx.x & 7;
    const size_t base = ((size_t)b * C_CH + g * 32) * N_PIX;
    const float* xp = x + base;
    const int TOT = 32 * N_PIX;

    float s = 0.f, s2 = 0.f;
    for (int i = threadIdx.x; i < TOT; i += 256) {
        float v = xp[i]; s += v; s2 += v * v;
    }
    #pragma unroll
    for (int o = 16; o > 0; o >>= 1) {
        s  += __shfl_xor_sync(0xFFFFFFFFu, s,  o);
        s2 += __shfl_xor_sync(0xFFFFFFFFu, s2, o);
    }
    __shared__ float shs[8], shs2[8], s_mean, s_inv, sgw[32], sgb[32];
    int wid = threadIdx.x >> 5, lid = threadIdx.x & 31;
    if (lid == 0) { shs[wid] = s; shs2[wid] = s2; }
    __syncthreads();
    if (threadIdx.x == 0) {
        float ts = 0.f, ts2 = 0.f;
        #pragma unroll
        for (int i = 0; i < 8; i++) { ts += shs[i]; ts2 += shs2[i]; }
        float mean = ts / (float)TOT;
        float var  = ts2 / (float)TOT - mean * mean;
        s_mean = mean; s_inv = rsqrtf(var + 1e-5f);
    }
    if (threadIdx.x < 32) { sgw[threadIdx.x] = gw[g * 32 + threadIdx.x]; sgb[threadIdx.x] = gb[g * 32 + threadIdx.x]; }
    __syncthreads();
    float mean = s_mean, inv = s_inv;

    for (int rep = 0; rep < 16; rep++) {
        int n = threadIdx.x + (rep << 8);
        uint32_t hb[16];
        #pragma unroll
        for (int c2 = 0; c2 < 16; c2++) {
            int c = c2 * 2;
            float v0 = (xp[(size_t)c * N_PIX + n]       - mean) * inv * sgw[c]     + sgb[c];
            float v1 = (xp[(size_t)(c + 1) * N_PIX + n] - mean) * inv * sgw[c + 1] + sgb[c + 1];
            hb[c2] = pk(hbits(v0), hbits(v1));
        }
        size_t di = ((size_t)b * N_PIX + n) * C_CH + g * 32;
        #pragma unroll
        for (int q = 0; q < 4; q++)
            *(uint4*)(xn + di + q * 8) = make_uint4(hb[q*4], hb[q*4+1], hb[q*4+2], hb[q*4+3]);
    }
}

// ---------------- rowsum reduce ----------------
__global__ void __launch_bounds__(256) rowsum_reduce(const float* __restrict__ part,
                                                     float* __restrict__ rsum) {
    int gw = (blockIdx.x * 256 + threadIdx.x) >> 5;
    int lane = threadIdx.x & 31;
    const float* p = part + (size_t)gw * 64;
    float s = p[lane] + p[lane + 32];
    #pragma unroll
    for (int o = 16; o > 0; o >>= 1) s += __shfl_xor_sync(0xFFFFFFFFu, s, o);
    if (lane == 0) rsum[gw] = 1.0f / s;
}

// ---------------- chunk loader: K-chunk 64, swizzled 128B rows ----------------
template <int ASPLIT>
__device__ __forceinline__ void load_chunk(uint32_t st, int k0,
                                           const u16* Ahb, const u16* Alb,
                                           const u16* Bb,
                                           int lda, int ldb, int tid) {
    const uint32_t BOFF = (1 + ASPLIT) * PIECE;
    #pragma unroll
    for (int it = 0; it < 4; it++) {
        int id = tid + (it << 8);
        int row = id >> 3, kc = id & 7;
        uint32_t off = (uint32_t)(row << 7) + (uint32_t)((kc << 4) ^ ((row & 7) << 4));
        size_t ga = (size_t)row * lda + k0 + kc * 8;
        size_t gb2 = (size_t)row * ldb + k0 + kc * 8;
        cpa16(st + off, Ahb + ga);
        if (ASPLIT) cpa16(st + PIECE + off, Alb + ga);
        cpa16(st + BOFF + off, Bb + gb2);
    }
}

// ---------------- fp16 mma.sync GEMM ----------------
// D[m,n] = sum_k A(m,k)*B(n,k); 128x128 tile; k-major; B always plain fp16.
// ASPLIT=1: A = Ah+Al (2 MMA/16k, 2-stage);  ASPLIT=0: A plain (1 MMA/16k, 3-stage).
// EPI: 0 scores (exp(alpha*S) -> plain P + partial sums), 1 AV (scale by rsum, plain store),
//      2 qkv (bias; q/k transposed plain, v plain), 3 proj (bias + resid, fp32)
template <int ASPLIT, int EPI>
__global__ void __launch_bounds__(256, 2)
gemm_mma(const u16* __restrict__ Ah, const u16* __restrict__ Al, long long sA, int lda,
         const u16* __restrict__ Bb, long long sB, int ldb,
         int K, int ldc, long long sOut, float alpha,
         const float* __restrict__ bias, const float* __restrict__ resid,
         float* __restrict__ outF,
         u16* __restrict__ o1, u16* __restrict__ o2, u16* __restrict__ o3) {
    extern __shared__ __align__(16) char smem[];
    const int tid = threadIdx.x;
    const int wid = tid >> 5, lane = tid & 31;
    const int wm = wid >> 1, wn = wid & 1;
    const int m0 = blockIdx.y * 128, n0 = blockIdx.x * 128, bz = blockIdx.z;

    const int NSTAGE = ASPLIT ? 2 : 3;
    const int STAGE  = (2 + ASPLIT) * PIECE;
    const int BOFF   = (1 + ASPLIT) * PIECE;

    const u16* Ahb = Ah + sA * bz + (size_t)m0 * lda;
    const u16* Alb = ASPLIT ? (Al + sA * bz + (size_t)m0 * lda) : nullptr;
    const u16* Bpb = Bb + sB * bz + (size_t)n0 * ldb;

    const uint32_t sb = smem_u32(smem);

    float acc[2][8][4] = {};

    // ldmatrix lane addressing with XOR swizzle (128B rows)
    const int ar  = lane & 15;
    const int akb = (lane >> 4) << 4;                   // 0/16
    const int br  = (lane & 7) + ((lane >> 4) << 3);
    const int bkb = ((lane >> 3) & 1) << 4;
    uint32_t aBase[2], aXor[2], bBase[4], bXor[4];
    #pragma unroll
    for (int mt = 0; mt < 2; mt++) {
        int r = wm * 32 + mt * 16 + ar;
        aBase[mt] = (uint32_t)(r << 7);
        aXor[mt]  = (uint32_t)((r & 7) << 4);
    }
    #pragma unroll
    for (int nt2 = 0; nt2 < 4; nt2++) {
        int r = wn * 64 + nt2 * 16 + br;
        bBase[nt2] = (uint32_t)(r << 7);
        bXor[nt2]  = (uint32_t)((r & 7) << 4);
    }

    const int NC = K >> 6;
    // prologue: load stages 0..NSTAGE-2
    #pragma unroll
    for (int s = 0; s < 3; s++) {
        if (s < NSTAGE - 1) {
            load_chunk<ASPLIT>(sb + s * STAGE, s << 6, Ahb, Alb, Bpb, lda, ldb, tid);
            asm volatile("cp.async.commit_group;" ::: "memory");
        }
    }

    for (int c = 0; c < NC; c++) {
        int pf = c + NSTAGE - 1;
        if (pf < NC)
            load_chunk<ASPLIT>(sb + (pf % NSTAGE) * STAGE, pf << 6, Ahb, Alb, Bpb, lda, ldb, tid);
        asm volatile("cp.async.commit_group;" ::: "memory");
        if (ASPLIT) asm volatile("cp.async.wait_group 1;" ::: "memory");
        else        asm volatile("cp.async.wait_group 2;" ::: "memory");
        __syncthreads();
        uint32_t st = sb + (c % NSTAGE) * STAGE;
        #pragma unroll
        for (int ks = 0; ks < 4; ks++) {
            const uint32_t kcol = (uint32_t)(ks << 5);
            uint32_t a_h[2][4], a_l[2][4];
            #pragma unroll
            for (int mt = 0; mt < 2; mt++) {
                uint32_t col = (kcol + akb) ^ aXor[mt];
                ldmx4(a_h[mt], st + aBase[mt] + col);
                if (ASPLIT) ldmx4(a_l[mt], st + PIECE + aBase[mt] + col);
            }
            #pragma unroll
            for (int nt2 = 0; nt2 < 4; nt2++) {
                uint32_t b_f[4];
                uint32_t col = (kcol + bkb) ^ bXor[nt2];
                ldmx4(b_f, st + BOFF + bBase[nt2] + col);
                #pragma unroll
                for (int mt = 0; mt < 2; mt++) {
                    mma16816(acc[mt][nt2 * 2],     a_h[mt], b_f);
                    mma16816(acc[mt][nt2 * 2 + 1], a_h[mt], b_f + 2);
                }
                if (ASPLIT) {
                    #pragma unroll
                    for (int mt = 0; mt < 2; mt++) {
                        mma16816(acc[mt][nt2 * 2],     a_l[mt], b_f);
                        mma16816(acc[mt][nt2 * 2 + 1], a_l[mt], b_f + 2);
                    }
                }
            }
        }
        __syncthreads();
    }

    const int rB = lane >> 2;
    const int cB = (lane & 3) * 2;

    if (EPI == 0) {
        // exp(alpha*S) -> plain fp16 P + deterministic row partial sums
        u16* P = o1 + sOut * bz;
        float* part = outF + (size_t)bz * N_PIX * 64;
        #pragma unroll
        for (int mt = 0; mt < 2; mt++)
            #pragma unroll
            for (int h = 0; h < 2; h++) {
                int rowG = m0 + wm * 32 + mt * 16 + rB + h * 8;
                float rs = 0.f;
                #pragma unroll
                for (int nt = 0; nt < 8; nt++) {
                    int colG = n0 + wn * 64 + nt * 8 + cB;
                    float e0 = __expf(acc[mt][nt][h * 2]     * alpha);
                    float e1 = __expf(acc[mt][nt][h * 2 + 1] * alpha);
                    rs += e0 + e1;
                    *(uint32_t*)(P + (size_t)rowG * ldc + colG) = pk(hbits(e0), hbits(e1));
                }
                rs += __shfl_xor_sync(0xFFFFFFFFu, rs, 1);
                rs += __shfl_xor_sync(0xFFFFFFFFu, rs, 2);
                if ((lane & 3) == 0)
                    part[(size_t)rowG * 64 + blockIdx.x * 2 + wn] = rs;
            }
    } else if (EPI == 1) {
        // AV: scale by reciprocal rowsum then plain store
        u16* O = o1 + sOut * bz;
        const float* rsum = outF + (size_t)bz * N_PIX;
        #pragma unroll
        for (int mt = 0; mt < 2; mt++)
            #pragma unroll
            for (int h = 0; h < 2; h++) {
                int rowG = m0 + wm * 32 + mt * 16 + rB + h * 8;
                float inv = rsum[rowG];
                #pragma unroll
                for (int nt = 0; nt < 8; nt++) {
                    int colG = n0 + wn * 64 + nt * 8 + cB;
                    *(uint32_t*)(O + (size_t)rowG * ldc + colG) =
                        pk(hbits(acc[mt][nt][h * 2] * inv), hbits(acc[mt][nt][h * 2 + 1] * inv));
                }
            }
    } else if (EPI == 3) {
        float* Ob = outF + sOut * bz;
        const float* Rb = resid + sOut * bz;
        #pragma unroll
        for (int mt = 0; mt < 2; mt++)
            #pragma unroll
            for (int nt = 0; nt < 8; nt++)
                #pragma unroll
                for (int h = 0; h < 2; h++) {
                    int rowG = m0 + wm * 32 + mt * 16 + rB + h * 8;
                    int colG = n0 + wn * 64 + nt * 8 + cB;
                    float bv = bias[rowG];
                    size_t di = (size_t)rowG * ldc + colG;
                    float2 rv = *(const float2*)(Rb + di);
                    float2 v = make_float2(acc[mt][nt][h * 2] + bv + rv.x,
                                           acc[mt][nt][h * 2 + 1] + bv + rv.y);
                    *(float2*)(Ob + di) = v;
                }
    } else {  // EPI 2: qkv
        int sect = m0 >> 8;
        int msub = m0 & 255;
        if (sect == 2) {   // v: plain store [c][4096] + bias
            u16* V = o3 + (size_t)1048576 * bz;
            #pragma unroll
            for (int mt = 0; mt < 2; mt++)
                #pragma unroll
                for (int nt = 0; nt < 8; nt++)
                    #pragma unroll
                    for (int h = 0; h < 2; h++) {
                        int rowL = wm * 32 + mt * 16 + rB + h * 8;
                        float bv = bias[m0 + rowL];
                        int colG = n0 + wn * 64 + nt * 8 + cB;
                        *(uint32_t*)(V + (size_t)(msub + rowL) * N_PIX + colG) =
                            pk(hbits(acc[mt][nt][h * 2] + bv), hbits(acc[mt][nt][h * 2 + 1] + bv));
                    }
        } else {           // q/k: transpose via SMEM bounce -> plain [n][256]
            u16* D = (sect ? o2 : o1) + (size_t)1048576 * bz;
            float* tsm = (float*)smem;
            __syncthreads();
            #pragma unroll
            for (int mt = 0; mt < 2; mt++)
                #pragma unroll
                for (int h = 0; h < 2; h++) {
                    int rowL = wm * 32 + mt * 16 + rB + h * 8;
                    float bv = bias[m0 + rowL];
                    #pragma unroll
                    for (int nt = 0; nt < 8; nt++) {
                        int colL = wn * 64 + nt * 8 + cB;
                        tsm[rowL * 133 + colL]     = acc[mt][nt][h * 2] + bv;
                        tsm[rowL * 133 + colL + 1] = acc[mt][nt][h * 2 + 1] + bv;
                    }
                }
            __syncthreads();
            #pragma unroll
            for (int it = 0; it < 32; it++) {
                int lin = tid + (it << 8);
                int n  = lin >> 6;
                int op = (lin & 63) << 1;
                float f0 = tsm[op * 133 + n];
                float f1 = tsm[(op + 1) * 133 + n];
                *(uint32_t*)(D + (size_t)(n0 + n) * C_CH + msub + op) = pk(hbits(f0), hbits(f1));
            }
        }
    }
}

// ---------------- launch ----------------
extern "C" void kernel_launch(void* const* d_in, const int* in_sizes, int n_in,
                              void* d_out, int out_size) {
    const float* x      = (const float*)d_in[0];
    const float* gn_w   = (const float*)d_in[1];
    const float* gn_b   = (const float*)d_in[2];
    const float* qkv_w  = (const float*)d_in[3];
    const float* qkv_b  = (const float*)d_in[4];
    const float* proj_w = (const float*)d_in[5];
    const float* proj_b = (const float*)d_in[6];
    float* out = (float*)d_out;

    u16 *wh, *wl, *ph, *pl, *xn, *qT, *kT, *v, *P, *O;
    float *part, *rsum;
    cudaGetSymbolAddress((void**)&wh, g_wh);   cudaGetSymbolAddress((void**)&wl, g_wl);
    cudaGetSymbolAddress((void**)&ph, g_ph);   cudaGetSymbolAddress((void**)&pl, g_pl);
    cudaGetSymbolAddress((void**)&xn, g_xn);
    cudaGetSymbolAddress((void**)&qT, g_qT);   cudaGetSymbolAddress((void**)&kT, g_kT);
    cudaGetSymbolAddress((void**)&v, g_v);     cudaGetSymbolAddress((void**)&P, g_P);
    cudaGetSymbolAddress((void**)&O, g_O);
    cudaGetSymbolAddress((void**)&part, g_part);
    cudaGetSymbolAddress((void**)&rsum, g_rsum);

    cudaFuncSetAttribute((const void*)gemm_mma<1, 2>, cudaFuncAttributeMaxDynamicSharedMemorySize, SMEM_A2);
    cudaFuncSetAttribute((const void*)gemm_mma<0, 0>, cudaFuncAttributeMaxDynamicSharedMemorySize, SMEM_A1);
    cudaFuncSetAttribute((const void*)gemm_mma<0, 1>, cudaFuncAttributeMaxDynamicSharedMemorySize, SMEM_A1);
    cudaFuncSetAttribute((const void*)gemm_mma<1, 3>, cudaFuncAttributeMaxDynamicSharedMemorySize, SMEM_A2);

    const long long sNC  = (long long)N_PIX * C_CH;      // 1M
    const long long sATT = (long long)N_PIX * N_PIX;     // 16M

    // 0) split weights
    split_w<<<1024, 256>>>(qkv_w, proj_w, wh, wl, ph, pl);

    // 1) GroupNorm -> xn^T plain fp16
    gn_plain<<<64, 256>>>(x, gn_w, gn_b, xn);

    // 2) QKV (A=W split, B=xn plain): -> q/k plain T, v plain
    gemm_mma<1, 2><<<dim3(32, 6, B_SZ), 256, SMEM_A2>>>(
        wh, wl, 0, C_CH, xn, sNC, C_CH, C_CH, 0, 0, 1.0f,
        qkv_b, nullptr, nullptr, qT, kT, v);

    // 3) scores+exp (all plain): P~[i,j] = exp((1/16) sum_c qT[i,c] kT[j,c]) + partial sums
    gemm_mma<0, 0><<<dim3(32, 32, B_SZ), 256, SMEM_A1>>>(
        qT, nullptr, sNC, C_CH, kT, sNC, C_CH, C_CH, N_PIX, sATT, 0.0625f,
        nullptr, nullptr, part, P, nullptr, nullptr);

    // 4) rowsum reduce -> reciprocal sums
    rowsum_reduce<<<(B_SZ * N_PIX) / 8, 256>>>(part, rsum);

    // 5) AV (all plain): O[i,c] = (sum_m P~[i,m] v[c,m]) / rowsum_i -> plain store [i][c]
    gemm_mma<0, 1><<<dim3(2, 32, B_SZ), 256, SMEM_A1>>>(
        P, nullptr, sATT, N_PIX, v, sNC, N_PIX, N_PIX, C_CH, sNC, 1.0f,
        nullptr, nullptr, rsum, O, nullptr, nullptr);

    // 6) proj (A=P split, B=O plain): out[o,i] = sum_c Pw[o,c] O[i,c] + pb[o] + x
    gemm_mma<1, 3><<<dim3(32, 2, B_SZ), 256, SMEM_A2>>>(
        ph, pl, 0, C_CH, O, sNC, C_CH, C_CH, N_PIX, sNC, 1.0f,
        proj_b, x, out, nullptr, nullptr, nullptr);
}

// round 11
// speedup vs baseline: 7.2615x; 1.0212x over previous
#include <cuda_runtime.h>
#include <cuda_fp16.h>
#include <cstdint>

#define B_SZ  8
#define C_CH  256
#define N_PIX 4096

typedef unsigned short u16;

// ---------------- scratch (device globals) ----------------
__device__ u16 g_wh[768 * 256],  g_wl[768 * 256];                        // qkv W split
__device__ u16 g_ph[256 * 256],  g_pl[256 * 256];                        // proj W split
__device__ u16 g_xn[B_SZ * N_PIX * C_CH];                                // xn^T [b][n][c] plain
__device__ u16 g_qT[B_SZ * N_PIX * C_CH];                                // q^T plain
__device__ u16 g_kT[B_SZ * N_PIX * C_CH];                                // k^T plain
__device__ u16 g_v [B_SZ * C_CH * N_PIX];                                // v [b][c][m] plain
__device__ u16 g_P [(size_t)B_SZ * N_PIX * N_PIX];                       // P~ plain (256MB)
__device__ float g_part[(size_t)B_SZ * N_PIX * 64];                      // row partial sums
__device__ float g_rsum[B_SZ * N_PIX];                                   // reciprocal row sums
__device__ u16 g_O [B_SZ * N_PIX * C_CH];                                // O [b][i][c] plain

// ---------------- helpers ----------------
__device__ __forceinline__ uint32_t smem_u32(const void* p) {
    uint32_t a;
    asm("{ .reg .u64 t; cvta.to.shared.u64 t, %1; cvt.u32.u64 %0, t; }" : "=r"(a) : "l"(p));
    return a;
}
__device__ __forceinline__ u16 hbits(float v) {
    return __half_as_ushort(__float2half_rn(v));
}
__device__ __forceinline__ float hval(u16 u) { return __half2float(__ushort_as_half(u)); }
__device__ __forceinline__ uint32_t pk(u16 a, u16 b) { return (uint32_t)a | ((uint32_t)b << 16); }
__device__ __forceinline__ void cpa16(uint32_t dst, const void* src) {
    asm volatile("cp.async.cg.shared.global [%0], [%1], 16;" :: "r"(dst), "l"(src));
}
__device__ __forceinline__ void ldmx4(uint32_t* r, uint32_t addr) {
    asm volatile("ldmatrix.sync.aligned.m8n8.x4.shared.b16 {%0,%1,%2,%3}, [%4];"
                 : "=r"(r[0]), "=r"(r[1]), "=r"(r[2]), "=r"(r[3]) : "r"(addr));
}
__device__ __forceinline__ void mma16816(float* c, const uint32_t* a, const uint32_t* b) {
    asm volatile("mma.sync.aligned.m16n8k16.row.col.f32.f16.f16.f32 "
                 "{%0,%1,%2,%3},{%4,%5,%6,%7},{%8,%9},{%0,%1,%2,%3};"
                 : "+f"(c[0]), "+f"(c[1]), "+f"(c[2]), "+f"(c[3])
                 : "r"(a[0]), "r"(a[1]), "r"(a[2]), "r"(a[3]), "r"(b[0]), "r"(b[1]));
}

// K-chunk = 64: piece = 128 rows x 128B (swizzled), 16KB
#define PIECE 16384
#define SMEM_A1 98304   // ASPLIT=0: 3 stages * 2 pieces
#define SMEM_A2 98304   // ASPLIT=1: 2 stages * 3 pieces (covers 68096B transpose bounce)

// ---------------- prep: split weights (fp16) ----------------
__global__ void split_w(const float* __restrict__ qw, const float* __restrict__ pw,
                        u16* qh, u16* ql, u16* ph_, u16* pl_) {
    int i = blockIdx.x * 256 + threadIdx.x;
    if (i < 768 * 256) {
        float v = qw[i];
        u16 h = hbits(v);
        qh[i] = h; ql[i] = hbits(v - hval(h));
    } else {
        int j = i - 768 * 256;
        float v = pw[j];
        u16 h = hbits(v);
        ph_[j] = h; pl_[j] = hbits(v - hval(h));
    }
}

// ---------------- GroupNorm -> plain fp16 transposed xn^T [b][n][c] ----------------
__global__ void __launch_bounds__(256) gn_plain(const float* __restrict__ x,
                                                const float* __restrict__ gw,
                                                const float* __restrict__ gb,
                                                u16* __restrict__ xn) {
    int b = blockIdx.x >> 3, g = blockIdx.x & 7;
    const size_t base = ((size_t)b * C_CH + g * 32) * N_PIX;
    const float* xp = x + base;
    const int TOT = 32 * N_PIX;

    float s = 0.f, s2 = 0.f;
    for (int i = threadIdx.x; i < TOT; i += 256) {
        float v = xp[i]; s += v; s2 += v * v;
    }
    #pragma unroll
    for (int o = 16; o > 0; o >>= 1) {
        s  += __shfl_xor_sync(0xFFFFFFFFu, s,  o);
        s2 += __shfl_xor_sync(0xFFFFFFFFu, s2, o);
    }
    __shared__ float shs[8], shs2[8], s_mean, s_inv, sgw[32], sgb[32];
    int wid = threadIdx.x >> 5, lid = threadIdx.x & 31;
    if (lid == 0) { shs[wid] = s; shs2[wid] = s2; }
    __syncthreads();
    if (threadIdx.x == 0) {
        float ts = 0.f, ts2 = 0.f;
        #pragma unroll
        for (int i = 0; i < 8; i++) { ts += shs[i]; ts2 += shs2[i]; }
        float mean = ts / (float)TOT;
        float var  = ts2 / (float)TOT - mean * mean;
        s_mean = mean; s_inv = rsqrtf(var + 1e-5f);
    }
    if (threadIdx.x < 32) { sgw[threadIdx.x] = gw[g * 32 + threadIdx.x]; sgb[threadIdx.x] = gb[g * 32 + threadIdx.x]; }
    __syncthreads();
    float mean = s_mean, inv = s_inv;

    for (int rep = 0; rep < 16; rep++) {
        int n = threadIdx.x + (rep << 8);
        uint32_t hb[16];
        #pragma unroll
        for (int c2 = 0; c2 < 16; c2++) {
            int c = c2 * 2;
            float v0 = (xp[(size_t)c * N_PIX + n]       - mean) * inv * sgw[c]     + sgb[c];
            float v1 = (xp[(size_t)(c + 1) * N_PIX + n] - mean) * inv * sgw[c + 1] + sgb[c + 1];
            hb[c2] = pk(hbits(v0), hbits(v1));
        }
        size_t di = ((size_t)b * N_PIX + n) * C_CH + g * 32;
        #pragma unroll
        for (int q = 0; q < 4; q++)
            *(uint4*)(xn + di + q * 8) = make_uint4(hb[q*4], hb[q*4+1], hb[q*4+2], hb[q*4+3]);
    }
}

// ---------------- rowsum reduce ----------------
__global__ void __launch_bounds__(256) rowsum_reduce(const float* __restrict__ part,
                                                     float* __restrict__ rsum) {
    int gw = (blockIdx.x * 256 + threadIdx.x) >> 5;
    int lane = threadIdx.x & 31;
    const float* p = part + (size_t)gw * 64;
    float s = p[lane] + p[lane + 32];
    #pragma unroll
    for (int o = 16; o > 0; o >>= 1) s += __shfl_xor_sync(0xFFFFFFFFu, s, o);
    if (lane == 0) rsum[gw] = 1.0f / s;
}

// ---------------- fp16 mma.sync GEMM ----------------
// D[m,n] = sum_k A(m,k)*B(n,k); 128x128 tile; k-major; B always plain fp16.
// ASPLIT=1: A = Ah+Al (2 MMA/16k, 2-stage);  ASPLIT=0: A plain (1 MMA/16k, 3-stage).
// EPI: 0 scores (exp(alpha*S) -> plain P + partial sums), 1 AV (scale by rsum, plain store),
//      2 qkv (bias; q/k transposed plain, v plain), 3 proj (bias + resid, fp32)
template <int ASPLIT, int EPI>
__global__ void __launch_bounds__(256, 2)
gemm_mma(const u16* __restrict__ Ah, const u16* __restrict__ Al, long long sA, int lda,
         const u16* __restrict__ Bb, long long sB, int ldb,
         int K, int ldc, long long sOut, float alpha,
         const float* __restrict__ bias, const float* __restrict__ resid,
         float* __restrict__ outF,
         u16* __restrict__ o1, u16* __restrict__ o2, u16* __restrict__ o3) {
    extern __shared__ __align__(16) char smem[];
    const int tid = threadIdx.x;
    const int wid = tid >> 5, lane = tid & 31;
    const int wm = wid >> 1, wn = wid & 1;
    const int m0 = blockIdx.y * 128, n0 = blockIdx.x * 128, bz = blockIdx.z;

    const int NSTAGE = ASPLIT ? 2 : 3;
    const int STAGE  = (2 + ASPLIT) * PIECE;
    const int BOFF   = (1 + ASPLIT) * PIECE;

    const u16* Ahb = Ah + sA * bz + (size_t)m0 * lda;
    const u16* Alb = ASPLIT ? (Al + sA * bz + (size_t)m0 * lda) : nullptr;
    const u16* Bpb = Bb + sB * bz + (size_t)n0 * ldb;

    const uint32_t sb = smem_u32(smem);

    float acc[2][8][4] = {};

    // ---- precomputed loader offsets (loop-invariant) ----
    uint32_t dstOff[4];   // swizzled smem offset within a piece
    uint32_t gOffA[4], gOffB[4];  // element offsets within a chunk row-block
    #pragma unroll
    for (int it = 0; it < 4; it++) {
        int id = tid + (it << 8);
        int row = id >> 3, kc = id & 7;
        dstOff[it] = (uint32_t)(row << 7) + (uint32_t)((kc << 4) ^ ((row & 7) << 4));
        gOffA[it] = (uint32_t)(row * lda + kc * 8);
        gOffB[it] = (uint32_t)(row * ldb + kc * 8);
    }

    // ---- precomputed ldmatrix offsets (swizzle folded in) ----
    const int ar  = lane & 15;
    const int akb = (lane >> 4) << 4;
    const int br  = (lane & 7) + ((lane >> 4) << 3);
    const int bkb = ((lane >> 3) & 1) << 4;
    uint32_t aOff[2][4], bOff[4][4];
    #pragma unroll
    for (int mt = 0; mt < 2; mt++) {
        int r = wm * 32 + mt * 16 + ar;
        #pragma unroll
        for (int ks = 0; ks < 4; ks++)
            aOff[mt][ks] = (uint32_t)(r << 7) + (uint32_t)(((ks << 5) + akb) ^ ((r & 7) << 4));
    }
    #pragma unroll
    for (int nt2 = 0; nt2 < 4; nt2++) {
        int r = wn * 64 + nt2 * 16 + br;
        #pragma unroll
        for (int ks = 0; ks < 4; ks++)
            bOff[nt2][ks] = (uint32_t)BOFF + (uint32_t)(r << 7) + (uint32_t)(((ks << 5) + bkb) ^ ((r & 7) << 4));
    }

    const int NC = K >> 6;

    // prologue: load stages 0..NSTAGE-2
    #pragma unroll
    for (int s = 0; s < 2; s++) {
        if (s < NSTAGE - 1) {
            uint32_t stB = sb + s * STAGE;
            int k0 = s << 6;
            #pragma unroll
            for (int it = 0; it < 4; it++) {
                cpa16(stB + dstOff[it], Ahb + k0 + gOffA[it]);
                if (ASPLIT) cpa16(stB + PIECE + dstOff[it], Alb + k0 + gOffA[it]);
                cpa16(stB + BOFF + dstOff[it], Bpb + k0 + gOffB[it]);
            }
            asm volatile("cp.async.commit_group;" ::: "memory");
        }
    }

    for (int c = 0; c < NC; c++) {
        if (ASPLIT) asm volatile("cp.async.wait_group 0;" ::: "memory");
        else        asm volatile("cp.async.wait_group 1;" ::: "memory");
        __syncthreads();
        // prefetch after barrier: target stage == stage read at iter c-1, now safe
        int pf = c + NSTAGE - 1;
        if (pf < NC) {
            uint32_t stB = sb + (pf % NSTAGE) * STAGE;
            int k0 = pf << 6;
            #pragma unroll
            for (int it = 0; it < 4; it++) {
                cpa16(stB + dstOff[it], Ahb + k0 + gOffA[it]);
                if (ASPLIT) cpa16(stB + PIECE + dstOff[it], Alb + k0 + gOffA[it]);
                cpa16(stB + BOFF + dstOff[it], Bpb + k0 + gOffB[it]);
            }
        }
        asm volatile("cp.async.commit_group;" ::: "memory");

        uint32_t st = sb + (c % NSTAGE) * STAGE;
        #pragma unroll
        for (int ks = 0; ks < 4; ks++) {
            uint32_t a_h[2][4], a_l[2][4];
            #pragma unroll
            for (int mt = 0; mt < 2; mt++) {
                ldmx4(a_h[mt], st + aOff[mt][ks]);
                if (ASPLIT) ldmx4(a_l[mt], st + PIECE + aOff[mt][ks]);
            }
            #pragma unroll
            for (int nt2 = 0; nt2 < 4; nt2++) {
                uint32_t b_f[4];
                ldmx4(b_f, st + bOff[nt2][ks]);
                #pragma unroll
                for (int mt = 0; mt < 2; mt++) {
                    mma16816(acc[mt][nt2 * 2],     a_h[mt], b_f);
                    mma16816(acc[mt][nt2 * 2 + 1], a_h[mt], b_f + 2);
                }
                if (ASPLIT) {
                    #pragma unroll
                    for (int mt = 0; mt < 2; mt++) {
                        mma16816(acc[mt][nt2 * 2],     a_l[mt], b_f);
                        mma16816(acc[mt][nt2 * 2 + 1], a_l[mt], b_f + 2);
                    }
                }
            }
        }
    }

    const int rB = lane >> 2;
    const int cB = (lane & 3) * 2;

    if (EPI == 0) {
        // exp(alpha*S) -> plain fp16 P + deterministic row partial sums
        u16* P = o1 + sOut * bz;
        float* part = outF + (size_t)bz * N_PIX * 64;
        #pragma unroll
        for (int mt = 0; mt < 2; mt++)
            #pragma unroll
            for (int h = 0; h < 2; h++) {
                int rowG = m0 + wm * 32 + mt * 16 + rB + h * 8;
                float rs = 0.f;
                #pragma unroll
                for (int nt = 0; nt < 8; nt++) {
                    int colG = n0 + wn * 64 + nt * 8 + cB;
                    float e0 = __expf(acc[mt][nt][h * 2]     * alpha);
                    float e1 = __expf(acc[mt][nt][h * 2 + 1] * alpha);
                    rs += e0 + e1;
                    *(uint32_t*)(P + (size_t)rowG * ldc + colG) = pk(hbits(e0), hbits(e1));
                }
                rs += __shfl_xor_sync(0xFFFFFFFFu, rs, 1);
                rs += __shfl_xor_sync(0xFFFFFFFFu, rs, 2);
                if ((lane & 3) == 0)
                    part[(size_t)rowG * 64 + blockIdx.x * 2 + wn] = rs;
            }
    } else if (EPI == 1) {
        // AV: scale by reciprocal rowsum then plain store
        u16* O = o1 + sOut * bz;
        const float* rsum = outF + (size_t)bz * N_PIX;
        #pragma unroll
        for (int mt = 0; mt < 2; mt++)
            #pragma unroll
            for (int h = 0; h < 2; h++) {
                int rowG = m0 + wm * 32 + mt * 16 + rB + h * 8;
                float inv = rsum[rowG];
                #pragma unroll
                for (int nt = 0; nt < 8; nt++) {
                    int colG = n0 + wn * 64 + nt * 8 + cB;
                    *(uint32_t*)(O + (size_t)rowG * ldc + colG) =
                        pk(hbits(acc[mt][nt][h * 2] * inv), hbits(acc[mt][nt][h * 2 + 1] * inv));
                }
            }
    } else if (EPI == 3) {
        float* Ob = outF + sOut * bz;
        const float* Rb = resid + sOut * bz;
        #pragma unroll
        for (int mt = 0; mt < 2; mt++)
            #pragma unroll
            for (int nt = 0; nt < 8; nt++)
                #pragma unroll
                for (int h = 0; h < 2; h++) {
                    int rowG = m0 + wm * 32 + mt * 16 + rB + h * 8;
                    int colG = n0 + wn * 64 + nt * 8 + cB;
                    float bv = bias[rowG];
                    size_t di = (size_t)rowG * ldc + colG;
                    float2 rv = *(const float2*)(Rb + di);
                    float2 v = make_float2(acc[mt][nt][h * 2] + bv + rv.x,
                                           acc[mt][nt][h * 2 + 1] + bv + rv.y);
                    *(float2*)(Ob + di) = v;
                }
    } else {  // EPI 2: qkv
        int sect = m0 >> 8;
        int msub = m0 & 255;
        if (sect == 2) {   // v: plain store [c][4096] + bias
            u16* V = o3 + (size_t)1048576 * bz;
            #pragma unroll
            for (int mt = 0; mt < 2; mt++)
                #pragma unroll
                for (int nt = 0; nt < 8; nt++)
                    #pragma unroll
                    for (int h = 0; h < 2; h++) {
                        int rowL = wm * 32 + mt * 16 + rB + h * 8;
                        float bv = bias[m0 + rowL];
                        int colG = n0 + wn * 64 + nt * 8 + cB;
                        *(uint32_t*)(V + (size_t)(msub + rowL) * N_PIX + colG) =
                            pk(hbits(acc[mt][nt][h * 2] + bv), hbits(acc[mt][nt][h * 2 + 1] + bv));
                    }
        } else {           // q/k: transpose via SMEM bounce -> plain [n][256]
            u16* D = (sect ? o2 : o1) + (size_t)1048576 * bz;
            float* tsm = (float*)smem;
            __syncthreads();
            #pragma unroll
            for (int mt = 0; mt < 2; mt++)
                #pragma unroll
                for (int h = 0; h < 2; h++) {
                    int rowL = wm * 32 + mt * 16 + rB + h * 8;
                    float bv = bias[m0 + rowL];
                    #pragma unroll
                    for (int nt = 0; nt < 8; nt++) {
                        int colL = wn * 64 + nt * 8 + cB;
                        tsm[rowL * 133 + colL]     = acc[mt][nt][h * 2] + bv;
                        tsm[rowL * 133 + colL + 1] = acc[mt][nt][h * 2 + 1] + bv;
                    }
                }
            __syncthreads();
            #pragma unroll
            for (int it = 0; it < 32; it++) {
                int lin = tid + (it << 8);
                int n  = lin >> 6;
                int op = (lin & 63) << 1;
                float f0 = tsm[op * 133 + n];
                float f1 = tsm[(op + 1) * 133 + n];
                *(uint32_t*)(D + (size_t)(n0 + n) * C_CH + msub + op) = pk(hbits(f0), hbits(f1));
            }
        }
    }
}

// ---------------- launch ----------------
extern "C" void kernel_launch(void* const* d_in, const int* in_sizes, int n_in,
                              void* d_out, int out_size) {
    const float* x      = (const float*)d_in[0];
    const float* gn_w   = (const float*)d_in[1];
    const float* gn_b   = (const float*)d_in[2];
    const float* qkv_w  = (const float*)d_in[3];
    const float* qkv_b  = (const float*)d_in[4];
    const float* proj_w = (const float*)d_in[5];
    const float* proj_b = (const float*)d_in[6];
    float* out = (float*)d_out;

    u16 *wh, *wl, *ph, *pl, *xn, *qT, *kT, *v, *P, *O;
    float *part, *rsum;
    cudaGetSymbolAddress((void**)&wh, g_wh);   cudaGetSymbolAddress((void**)&wl, g_wl);
    cudaGetSymbolAddress((void**)&ph, g_ph);   cudaGetSymbolAddress((void**)&pl, g_pl);
    cudaGetSymbolAddress((void**)&xn, g_xn);
    cudaGetSymbolAddress((void**)&qT, g_qT);   cudaGetSymbolAddress((void**)&kT, g_kT);
    cudaGetSymbolAddress((void**)&v, g_v);     cudaGetSymbolAddress((void**)&P, g_P);
    cudaGetSymbolAddress((void**)&O, g_O);
    cudaGetSymbolAddress((void**)&part, g_part);
    cudaGetSymbolAddress((void**)&rsum, g_rsum);

    cudaFuncSetAttribute((const void*)gemm_mma<1, 2>, cudaFuncAttributeMaxDynamicSharedMemorySize, SMEM_A2);
    cudaFuncSetAttribute((const void*)gemm_mma<0, 0>, cudaFuncAttributeMaxDynamicSharedMemorySize, SMEM_A1);
    cudaFuncSetAttribute((const void*)gemm_mma<0, 1>, cudaFuncAttributeMaxDynamicSharedMemorySize, SMEM_A1);
    cudaFuncSetAttribute((const void*)gemm_mma<1, 3>, cudaFuncAttributeMaxDynamicSharedMemorySize, SMEM_A2);

    const long long sNC  = (long long)N_PIX * C_CH;      // 1M
    const long long sATT = (long long)N_PIX * N_PIX;     // 16M

    // 0) split weights
    split_w<<<1024, 256>>>(qkv_w, proj_w, wh, wl, ph, pl);

    // 1) GroupNorm -> xn^T plain fp16
    gn_plain<<<64, 256>>>(x, gn_w, gn_b, xn);

    // 2) QKV (A=W split, B=xn plain): -> q/k plain T, v plain
    gemm_mma<1, 2><<<dim3(32, 6, B_SZ), 256, SMEM_A2>>>(
        wh, wl, 0, C_CH, xn, sNC, C_CH, C_CH, 0, 0, 1.0f,
        qkv_b, nullptr, nullptr, qT, kT, v);

    // 3) scores+exp (all plain): P~[i,j] = exp((1/16) sum_c qT[i,c] kT[j,c]) + partial sums
    gemm_mma<0, 0><<<dim3(32, 32, B_SZ), 256, SMEM_A1>>>(
        qT, nullptr, sNC, C_CH, kT, sNC, C_CH, C_CH, N_PIX, sATT, 0.0625f,
        nullptr, nullptr, part, P, nullptr, nullptr);

    // 4) rowsum reduce -> reciprocal sums
    rowsum_reduce<<<(B_SZ * N_PIX) / 8, 256>>>(part, rsum);

    // 5) AV (all plain): O[i,c] = (sum_m P~[i,m] v[c,m]) / rowsum_i -> plain store [i][c]
    gemm_mma<0, 1><<<dim3(2, 32, B_SZ), 256, SMEM_A1>>>(
        P, nullptr, sATT, N_PIX, v, sNC, N_PIX, N_PIX, C_CH, sNC, 1.0f,
        nullptr, nullptr, rsum, O, nullptr, nullptr);

    // 6) proj (A=P split, B=O plain): out[o,i] = sum_c Pw[o,c] O[i,c] + pb[o] + x
    gemm_mma<1, 3><<<dim3(32, 2, B_SZ), 256, SMEM_A2>>>(
        ph, pl, 0, C_CH, O, sNC, C_CH, C_CH, N_PIX, sNC, 1.0f,
        proj_b, x, out, nullptr, nullptr, nullptr);
}

// round 12
// speedup vs baseline: 7.2835x; 1.0030x over previous
#include <cuda_runtime.h>
#include <cuda_fp16.h>
#include <cstdint>

#define B_SZ  8
#define C_CH  256
#define N_PIX 4096

typedef unsigned short u16;

// ---------------- scratch (device globals) ----------------
__device__ u16 g_wh[768 * 256],  g_wl[768 * 256];                        // qkv W split
__device__ u16 g_ph[256 * 256],  g_pl[256 * 256];                        // proj W split
__device__ u16 g_xn[B_SZ * N_PIX * C_CH];                                // xn^T [b][n][c] plain
__device__ u16 g_qT[B_SZ * N_PIX * C_CH];                                // q^T plain
__device__ u16 g_kT[B_SZ * N_PIX * C_CH];                                // k^T plain
__device__ u16 g_v [B_SZ * C_CH * N_PIX];                                // v [b][c][m] plain
__device__ u16 g_P [(size_t)B_SZ * N_PIX * N_PIX];                       // P~ plain (256MB)
__device__ float g_part[(size_t)B_SZ * N_PIX * 64];                      // row partial sums
__device__ float g_rsum[B_SZ * N_PIX];                                   // reciprocal row sums
__device__ u16 g_O [B_SZ * N_PIX * C_CH];                                // O [b][i][c] plain

// ---------------- helpers ----------------
__device__ __forceinline__ uint32_t smem_u32(const void* p) {
    uint32_t a;
    asm("{ .reg .u64 t; cvta.to.shared.u64 t, %1; cvt.u32.u64 %0, t; }" : "=r"(a) : "l"(p));
    return a;
}
__device__ __forceinline__ u16 hbits(float v) {
    return __half_as_ushort(__float2half_rn(v));
}
__device__ __forceinline__ float hval(u16 u) { return __half2float(__ushort_as_half(u)); }
__device__ __forceinline__ uint32_t pk(u16 a, u16 b) { return (uint32_t)a | ((uint32_t)b << 16); }
__device__ __forceinline__ void cpa16(uint32_t dst, const void* src) {
    asm volatile("cp.async.cg.shared.global [%0], [%1], 16;" :: "r"(dst), "l"(src));
}
__device__ __forceinline__ void ldmx4(uint32_t* r, uint32_t addr) {
    asm volatile("ldmatrix.sync.aligned.m8n8.x4.shared.b16 {%0,%1,%2,%3}, [%4];"
                 : "=r"(r[0]), "=r"(r[1]), "=r"(r[2]), "=r"(r[3]) : "r"(addr));
}
__device__ __forceinline__ void mma16816(float* c, const uint32_t* a, const uint32_t* b) {
    asm volatile("mma.sync.aligned.m16n8k16.row.col.f32.f16.f16.f32 "
                 "{%0,%1,%2,%3},{%4,%5,%6,%7},{%8,%9},{%0,%1,%2,%3};"
                 : "+f"(c[0]), "+f"(c[1]), "+f"(c[2]), "+f"(c[3])
                 : "r"(a[0]), "r"(a[1]), "r"(a[2]), "r"(a[3]), "r"(b[0]), "r"(b[1]));
}

// K-chunk = 64: piece = 128 rows x 128B (swizzled), 16KB
#define PIECE 16384
#define SMEM_A1 98304   // ASPLIT=0: 3 stages * 2 pieces
#define SMEM_A2 98304   // ASPLIT=1: 2 stages * 3 pieces (covers 68096B transpose bounce)

// ---------------- prep: split weights (fp16) ----------------
__global__ void split_w(const float* __restrict__ qw, const float* __restrict__ pw,
                        u16* qh, u16* ql, u16* ph_, u16* pl_) {
    int i = blockIdx.x * 256 + threadIdx.x;
    if (i < 768 * 256) {
        float v = qw[i];
        u16 h = hbits(v);
        qh[i] = h; ql[i] = hbits(v - hval(h));
    } else {
        int j = i - 768 * 256;
        float v = pw[j];
        u16 h = hbits(v);
        ph_[j] = h; pl_[j] = hbits(v - hval(h));
    }
}

// ---------------- GroupNorm -> plain fp16 transposed xn^T [b][n][c] ----------------
__global__ void __launch_bounds__(256) gn_plain(const float* __restrict__ x,
                                                const float* __restrict__ gw,
                                                const float* __restrict__ gb,
                                                u16* __restrict__ xn) {
    int b = blockIdx.x >> 3, g = blockIdx.x & 7;
    const size_t base = ((size_t)b * C_CH + g * 32) * N_PIX;
    const float* xp = x + base;
    const int TOT = 32 * N_PIX;

    float s = 0.f, s2 = 0.f;
    for (int i = threadIdx.x; i < TOT; i += 256) {
        float v = xp[i]; s += v; s2 += v * v;
    }
    #pragma unroll
    for (int o = 16; o > 0; o >>= 1) {
        s  += __shfl_xor_sync(0xFFFFFFFFu, s,  o);
        s2 += __shfl_xor_sync(0xFFFFFFFFu, s2, o);
    }
    __shared__ float shs[8], shs2[8], s_mean, s_inv, sgw[32], sgb[32];
    int wid = threadIdx.x >> 5, lid = threadIdx.x & 31;
    if (lid == 0) { shs[wid] = s; shs2[wid] = s2; }
    __syncthreads();
    if (threadIdx.x == 0) {
        float ts = 0.f, ts2 = 0.f;
        #pragma unroll
        for (int i = 0; i < 8; i++) { ts += shs[i]; ts2 += shs2[i]; }
        float mean = ts / (float)TOT;
        float var  = ts2 / (float)TOT - mean * mean;
        s_mean = mean; s_inv = rsqrtf(var + 1e-5f);
    }
    if (threadIdx.x < 32) { sgw[threadIdx.x] = gw[g * 32 + threadIdx.x]; sgb[threadIdx.x] = gb[g * 32 + threadIdx.x]; }
    __syncthreads();
    float mean = s_mean, inv = s_inv;

    for (int rep = 0; rep < 16; rep++) {
        int n = threadIdx.x + (rep << 8);
        uint32_t hb[16];
        #pragma unroll
        for (int c2 = 0; c2 < 16; c2++) {
            int c = c2 * 2;
            float v0 = (xp[(size_t)c * N_PIX + n]       - mean) * inv * sgw[c]     + sgb[c];
            float v1 = (xp[(size_t)(c + 1) * N_PIX + n] - mean) * inv * sgw[c + 1] + sgb[c + 1];
            hb[c2] = pk(hbits(v0), hbits(v1));
        }
        size_t di = ((size_t)b * N_PIX + n) * C_CH + g * 32;
        #pragma unroll
        for (int q = 0; q < 4; q++)
            *(uint4*)(xn + di + q * 8) = make_uint4(hb[q*4], hb[q*4+1], hb[q*4+2], hb[q*4+3]);
    }
}

// ---------------- rowsum reduce ----------------
__global__ void __launch_bounds__(256) rowsum_reduce(const float* __restrict__ part,
                                                     float* __restrict__ rsum) {
    int gw = (blockIdx.x * 256 + threadIdx.x) >> 5;
    int lane = threadIdx.x & 31;
    const float* p = part + (size_t)gw * 64;
    float s = p[lane] + p[lane + 32];
    #pragma unroll
    for (int o = 16; o > 0; o >>= 1) s += __shfl_xor_sync(0xFFFFFFFFu, s, o);
    if (lane == 0) rsum[gw] = 1.0f / s;
}

// ---------------- fp16 mma.sync GEMM ----------------
// D[m,n] = sum_k A(m,k)*B(n,k); 128x128 tile; k-major; B always plain fp16.
// ASPLIT=1: A = Ah+Al (2 MMA/16k, 2-stage);  ASPLIT=0: A plain (1 MMA/16k, 3-stage).
// EPI: 0 scores (exp(alpha*S) -> plain P + partial sums), 1 AV (scale by rsum, plain store),
//      2 qkv (bias; q/k transposed plain, v plain), 3 proj (bias + resid, fp32)
template <int ASPLIT, int EPI>
__global__ void __launch_bounds__(256, 2)
gemm_mma(const u16* __restrict__ Ah, const u16* __restrict__ Al, long long sA, int lda,
         const u16* __restrict__ Bb, long long sB, int ldb,
         int K, int ldc, long long sOut, float alpha,
         const float* __restrict__ bias, const float* __restrict__ resid,
         float* __restrict__ outF,
         u16* __restrict__ o1, u16* __restrict__ o2, u16* __restrict__ o3) {
    extern __shared__ __align__(16) char smem[];
    const int tid = threadIdx.x;
    const int wid = tid >> 5, lane = tid & 31;
    const int wm = wid >> 1, wn = wid & 1;
    const int m0 = blockIdx.y * 128, n0 = blockIdx.x * 128, bz = blockIdx.z;

    const int NSTAGE = ASPLIT ? 2 : 3;
    const int STAGE  = (2 + ASPLIT) * PIECE;
    const int BOFF   = (1 + ASPLIT) * PIECE;

    const u16* Ahb = Ah + sA * bz + (size_t)m0 * lda;
    const u16* Alb = ASPLIT ? (Al + sA * bz + (size_t)m0 * lda) : nullptr;
    const u16* Bpb = Bb + sB * bz + (size_t)n0 * ldb;

    const uint32_t sb = smem_u32(smem);

    float acc[2][8][4] = {};

    // ---- precomputed loader offsets (loop-invariant) ----
    uint32_t dstOff[4];   // swizzled smem offset within a piece
    uint32_t gOffA[4], gOffB[4];  // element offsets within a chunk row-block
    #pragma unroll
    for (int it = 0; it < 4; it++) {
        int id = tid + (it << 8);
        int row = id >> 3, kc = id & 7;
        dstOff[it] = (uint32_t)(row << 7) + (uint32_t)((kc << 4) ^ ((row & 7) << 4));
        gOffA[it] = (uint32_t)(row * lda + kc * 8);
        gOffB[it] = (uint32_t)(row * ldb + kc * 8);
    }

    // ---- precomputed ldmatrix offsets (swizzle folded in) ----
    const int ar  = lane & 15;
    const int akb = (lane >> 4) << 4;
    const int br  = (lane & 7) + ((lane >> 4) << 3);
    const int bkb = ((lane >> 3) & 1) << 4;
    uint32_t aOff[2][4], bOff[4][4];
    #pragma unroll
    for (int mt = 0; mt < 2; mt++) {
        int r = wm * 32 + mt * 16 + ar;
        #pragma unroll
        for (int ks = 0; ks < 4; ks++)
            aOff[mt][ks] = (uint32_t)(r << 7) + (uint32_t)(((ks << 5) + akb) ^ ((r & 7) << 4));
    }
    #pragma unroll
    for (int nt2 = 0; nt2 < 4; nt2++) {
        int r = wn * 64 + nt2 * 16 + br;
        #pragma unroll
        for (int ks = 0; ks < 4; ks++)
            bOff[nt2][ks] = (uint32_t)BOFF + (uint32_t)(r << 7) + (uint32_t)(((ks << 5) + bkb) ^ ((r & 7) << 4));
    }

    const int NC = K >> 6;

    // prologue: load stages 0..NSTAGE-2
    #pragma unroll
    for (int s = 0; s < 2; s++) {
        if (s < NSTAGE - 1) {
            uint32_t stB = sb + s * STAGE;
            int k0 = s << 6;
            #pragma unroll
            for (int it = 0; it < 4; it++) {
                cpa16(stB + dstOff[it], Ahb + k0 + gOffA[it]);
                if (ASPLIT) cpa16(stB + PIECE + dstOff[it], Alb + k0 + gOffA[it]);
                cpa16(stB + BOFF + dstOff[it], Bpb + k0 + gOffB[it]);
            }
            asm volatile("cp.async.commit_group;" ::: "memory");
        }
    }

    for (int c = 0; c < NC; c++) {
        if (ASPLIT) asm volatile("cp.async.wait_group 0;" ::: "memory");
        else        asm volatile("cp.async.wait_group 1;" ::: "memory");
        __syncthreads();
        // prefetch after barrier: target stage == stage read at iter c-1, now safe
        int pf = c + NSTAGE - 1;
        if (pf < NC) {
            uint32_t stB = sb + (pf % NSTAGE) * STAGE;
            int k0 = pf << 6;
            #pragma unroll
            for (int it = 0; it < 4; it++) {
                cpa16(stB + dstOff[it], Ahb + k0 + gOffA[it]);
                if (ASPLIT) cpa16(stB + PIECE + dstOff[it], Alb + k0 + gOffA[it]);
                cpa16(stB + BOFF + dstOff[it], Bpb + k0 + gOffB[it]);
            }
        }
        asm volatile("cp.async.commit_group;" ::: "memory");

        uint32_t st = sb + (c % NSTAGE) * STAGE;
        #pragma unroll
        for (int ks = 0; ks < 4; ks++) {
            uint32_t a_h[2][4], a_l[2][4];
            #pragma unroll
            for (int mt = 0; mt < 2; mt++) {
                ldmx4(a_h[mt], st + aOff[mt][ks]);
                if (ASPLIT) ldmx4(a_l[mt], st + PIECE + aOff[mt][ks]);
            }
            #pragma unroll
            for (int nt2 = 0; nt2 < 4; nt2++) {
                uint32_t b_f[4];
                ldmx4(b_f, st + bOff[nt2][ks]);
                #pragma unroll
                for (int mt = 0; mt < 2; mt++) {
                    mma16816(acc[mt][nt2 * 2],     a_h[mt], b_f);
                    mma16816(acc[mt][nt2 * 2 + 1], a_h[mt], b_f + 2);
                }
                if (ASPLIT) {
                    #pragma unroll
                    for (int mt = 0; mt < 2; mt++) {
                        mma16816(acc[mt][nt2 * 2],     a_l[mt], b_f);
                        mma16816(acc[mt][nt2 * 2 + 1], a_l[mt], b_f + 2);
                    }
                }
            }
        }
    }

    const int rB = lane >> 2;
    const int cB = (lane & 3) * 2;

    if (EPI == 0) {
        // exp(alpha*S) -> plain fp16 P + deterministic row partial sums
        u16* P = o1 + sOut * bz;
        float* part = outF + (size_t)bz * N_PIX * 64;
        #pragma unroll
        for (int mt = 0; mt < 2; mt++)
            #pragma unroll
            for (int h = 0; h < 2; h++) {
                int rowG = m0 + wm * 32 + mt * 16 + rB + h * 8;
                float rs = 0.f;
                #pragma unroll
                for (int nt = 0; nt < 8; nt++) {
                    int colG = n0 + wn * 64 + nt * 8 + cB;
                    float e0 = __expf(acc[mt][nt][h * 2]     * alpha);
                    float e1 = __expf(acc[mt][nt][h * 2 + 1] * alpha);
                    rs += e0 + e1;
                    *(uint32_t*)(P + (size_t)rowG * ldc + colG) = pk(hbits(e0), hbits(e1));
                }
                rs += __shfl_xor_sync(0xFFFFFFFFu, rs, 1);
                rs += __shfl_xor_sync(0xFFFFFFFFu, rs, 2);
                if ((lane & 3) == 0)
                    part[(size_t)rowG * 64 + blockIdx.x * 2 + wn] = rs;
            }
    } else if (EPI == 1) {
        // AV: scale by reciprocal rowsum then plain store
        u16* O = o1 + sOut * bz;
        const float* rsum = outF + (size_t)bz * N_PIX;
        #pragma unroll
        for (int mt = 0; mt < 2; mt++)
            #pragma unroll
            for (int h = 0; h < 2; h++) {
                int rowG = m0 + wm * 32 + mt * 16 + rB + h * 8;
                float inv = rsum[rowG];
                #pragma unroll
                for (int nt = 0; nt < 8; nt++) {
                    int colG = n0 + wn * 64 + nt * 8 + cB;
                    *(uint32_t*)(O + (size_t)rowG * ldc + colG) =
                        pk(hbits(acc[mt][nt][h * 2] * inv), hbits(acc[mt][nt][h * 2 + 1] * inv));
                }
            }
    } else if (EPI == 3) {
        float* Ob = outF + sOut * bz;
        const float* Rb = resid + sOut * bz;
        #pragma unroll
        for (int mt = 0; mt < 2; mt++)
            #pragma unroll
            for (int nt = 0; nt < 8; nt++)
                #pragma unroll
                for (int h = 0; h < 2; h++) {
                    int rowG = m0 + wm * 32 + mt * 16 + rB + h * 8;
                    int colG = n0 + wn * 64 + nt * 8 + cB;
                    float bv = bias[rowG];
                    size_t di = (size_t)rowG * ldc + colG;
                    float2 rv = *(const float2*)(Rb + di);
                    float2 v = make_float2(acc[mt][nt][h * 2] + bv + rv.x,
                                           acc[mt][nt][h * 2 + 1] + bv + rv.y);
                    *(float2*)(Ob + di) = v;
                }
    } else {  // EPI 2: qkv
        int sect = m0 >> 8;
        int msub = m0 & 255;
        if (sect == 2) {   // v: plain store [c][4096] + bias
            u16* V = o3 + (size_t)1048576 * bz;
            #pragma unroll
            for (int mt = 0; mt < 2; mt++)
                #pragma unroll
                for (int nt = 0; nt < 8; nt++)
                    #pragma unroll
                    for (int h = 0; h < 2; h++) {
                        int rowL = wm * 32 + mt * 16 + rB + h * 8;
                        float bv = bias[m0 + rowL];
                        int colG = n0 + wn * 64 + nt * 8 + cB;
                        *(uint32_t*)(V + (size_t)(msub + rowL) * N_PIX + colG) =
                            pk(hbits(acc[mt][nt][h * 2] + bv), hbits(acc[mt][nt][h * 2 + 1] + bv));
                    }
        } else {           // q/k: transpose via SMEM bounce -> plain [n][256]
            u16* D = (sect ? o2 : o1) + (size_t)1048576 * bz;
            float* tsm = (float*)smem;
            __syncthreads();
            #pragma unroll
            for (int mt = 0; mt < 2; mt++)
                #pragma unroll
                for (int h = 0; h < 2; h++) {
                    int rowL = wm * 32 + mt * 16 + rB + h * 8;
                    float bv = bias[m0 + rowL];
                    #pragma unroll
                    for (int nt = 0; nt < 8; nt++) {
                        int colL = wn * 64 + nt * 8 + cB;
                        tsm[rowL * 133 + colL]     = acc[mt][nt][h * 2] + bv;
                        tsm[rowL * 133 + colL + 1] = acc[mt][nt][h * 2 + 1] + bv;
                    }
                }
            __syncthreads();
            #pragma unroll
            for (int it = 0; it < 32; it++) {
                int lin = tid + (it << 8);
                int n  = lin >> 6;
                int op = (lin & 63) << 1;
                float f0 = tsm[op * 133 + n];
                float f1 = tsm[(op + 1) * 133 + n];
                *(uint32_t*)(D + (size_t)(n0 + n) * C_CH + msub + op) = pk(hbits(f0), hbits(f1));
            }
        }
    }
}

// ---------------- launch ----------------
extern "C" void kernel_launch(void* const* d_in, const int* in_sizes, int n_in,
                              void* d_out, int out_size) {
    const float* x      = (const float*)d_in[0];
    const float* gn_w   = (const float*)d_in[1];
    const float* gn_b   = (const float*)d_in[2];
    const float* qkv_w  = (const float*)d_in[3];
    const float* qkv_b  = (const float*)d_in[4];
    const float* proj_w = (const float*)d_in[5];
    const float* proj_b = (const float*)d_in[6];
    float* out = (float*)d_out;

    u16 *wh, *wl, *ph, *pl, *xn, *qT, *kT, *v, *P, *O;
    float *part, *rsum;
    cudaGetSymbolAddress((void**)&wh, g_wh);   cudaGetSymbolAddress((void**)&wl, g_wl);
    cudaGetSymbolAddress((void**)&ph, g_ph);   cudaGetSymbolAddress((void**)&pl, g_pl);
    cudaGetSymbolAddress((void**)&xn, g_xn);
    cudaGetSymbolAddress((void**)&qT, g_qT);   cudaGetSymbolAddress((void**)&kT, g_kT);
    cudaGetSymbolAddress((void**)&v, g_v);     cudaGetSymbolAddress((void**)&P, g_P);
    cudaGetSymbolAddress((void**)&O, g_O);
    cudaGetSymbolAddress((void**)&part, g_part);
    cudaGetSymbolAddress((void**)&rsum, g_rsum);

    cudaFuncSetAttribute((const void*)gemm_mma<1, 2>, cudaFuncAttributeMaxDynamicSharedMemorySize, SMEM_A2);
    cudaFuncSetAttribute((const void*)gemm_mma<0, 0>, cudaFuncAttributeMaxDynamicSharedMemorySize, SMEM_A1);
    cudaFuncSetAttribute((const void*)gemm_mma<0, 1>, cudaFuncAttributeMaxDynamicSharedMemorySize, SMEM_A1);
    cudaFuncSetAttribute((const void*)gemm_mma<1, 3>, cudaFuncAttributeMaxDynamicSharedMemorySize, SMEM_A2);

    const long long sNC  = (long long)N_PIX * C_CH;      // 1M
    const long long sATT = (long long)N_PIX * N_PIX;     // 16M

    // 0) split weights
    split_w<<<1024, 256>>>(qkv_w, proj_w, wh, wl, ph, pl);

    // 1) GroupNorm -> xn^T plain fp16
    gn_plain<<<64, 256>>>(x, gn_w, gn_b, xn);

    // 2) QKV (A=W split, B=xn plain): -> q/k plain T, v plain
    gemm_mma<1, 2><<<dim3(32, 6, B_SZ), 256, SMEM_A2>>>(
        wh, wl, 0, C_CH, xn, sNC, C_CH, C_CH, 0, 0, 1.0f,
        qkv_b, nullptr, nullptr, qT, kT, v);

    // 3) scores+exp (all plain): P~[i,j] = exp((1/16) sum_c qT[i,c] kT[j,c]) + partial sums
    gemm_mma<0, 0><<<dim3(32, 32, B_SZ), 256, SMEM_A1>>>(
        qT, nullptr, sNC, C_CH, kT, sNC, C_CH, C_CH, N_PIX, sATT, 0.0625f,
        nullptr, nullptr, part, P, nullptr, nullptr);

    // 4) rowsum reduce -> reciprocal sums
    rowsum_reduce<<<(B_SZ * N_PIX) / 8, 256>>>(part, rsum);

    // 5) AV (all plain): O[i,c] = (sum_m P~[i,m] v[c,m]) / rowsum_i -> plain store [i][c]
    gemm_mma<0, 1><<<dim3(2, 32, B_SZ), 256, SMEM_A1>>>(
        P, nullptr, sATT, N_PIX, v, sNC, N_PIX, N_PIX, C_CH, sNC, 1.0f,
        nullptr, nullptr, rsum, O, nullptr, nullptr);

    // 6) proj (A=P split, B=O plain): out[o,i] = sum_c Pw[o,c] O[i,c] + pb[o] + x
    gemm_mma<1, 3><<<dim3(32, 2, B_SZ), 256, SMEM_A2>>>(
        ph, pl, 0, C_CH, O, sNC, C_CH, C_CH, N_PIX, sNC, 1.0f,
        proj_b, x, out, nullptr, nullptr, nullptr);
}